// round 1
// baseline (speedup 1.0000x reference)
#include <cuda_runtime.h>
#include <math.h>

#define BB   4
#define SS   2048
#define DD   1024
#define HH   16
#define DKK  64
#define DFFC 4096
#define NTOK (BB*SS)

// Scratch (allocation-free rule: __device__ globals)
__device__ float g_hidden[(size_t)NTOK*DD];
__device__ float g_q     [(size_t)NTOK*DD];
__device__ float g_k     [(size_t)NTOK*DD];
__device__ float g_attn  [(size_t)NTOK*DD];
__device__ float g_x2    [(size_t)NTOK*DD];
__device__ float g_h2    [(size_t)NTOK*DD];
__device__ float g_ffn   [(size_t)NTOK*DFFC];

// ---------------------------------------------------------------------------
// LayerNorm: one block per token, 256 threads, 4 floats/thread (float4).
// var = E[x^2] - mean^2 (mathematically identical to reference; fp32 ok here)
// ---------------------------------------------------------------------------
__global__ void __launch_bounds__(256) ln_kernel(
    const float* __restrict__ x, const float* __restrict__ g,
    const float* __restrict__ b, float* __restrict__ out)
{
    __shared__ float red[20];
    int t = blockIdx.x;
    int tid = threadIdx.x;
    float4 v = ((const float4*)(x + (size_t)t*DD))[tid];
    float s  = v.x + v.y + v.z + v.w;
    float s2 = v.x*v.x + v.y*v.y + v.z*v.z + v.w*v.w;
#pragma unroll
    for (int o = 16; o; o >>= 1) {
        s  += __shfl_xor_sync(0xffffffffu, s,  o);
        s2 += __shfl_xor_sync(0xffffffffu, s2, o);
    }
    int w = tid >> 5, l = tid & 31;
    if (l == 0) { red[w] = s; red[8 + w] = s2; }
    __syncthreads();
    if (tid == 0) {
        float a = 0.f, c = 0.f;
#pragma unroll
        for (int i = 0; i < 8; i++) { a += red[i]; c += red[8 + i]; }
        red[16] = a; red[17] = c;
    }
    __syncthreads();
    float mean = red[16] * (1.0f / DD);
    float var  = red[17] * (1.0f / DD) - mean * mean;
    float inv  = rsqrtf(var + 1e-5f);
    float4 gv = ((const float4*)g)[tid];
    float4 bv = ((const float4*)b)[tid];
    float4 o4;
    o4.x = (v.x - mean) * inv * gv.x + bv.x;
    o4.y = (v.y - mean) * inv * gv.y + bv.y;
    o4.z = (v.z - mean) * inv * gv.z + bv.z;
    o4.w = (v.w - mean) * inv * gv.w + bv.w;
    ((float4*)(out + (size_t)t*DD))[tid] = o4;
}

// ---------------------------------------------------------------------------
// SGEMM 128x128x8, 256 threads, 8x8 per thread, fused epilogue.
// epi: 0 = +bias ; 1 = +bias+residual ; 2 = gelu_exact(+bias)
// A: [M,K] row-major, B: [K,N] row-major, C: [M,N]
// ---------------------------------------------------------------------------
__global__ void __launch_bounds__(256) sgemm_kernel(
    const float* __restrict__ A, const float* __restrict__ B,
    const float* __restrict__ bias, const float* __restrict__ res,
    float* __restrict__ C, int M, int N, int K, int epi)
{
    __shared__ float As[8][132];   // [k][m], padded
    __shared__ float Bs[8][132];   // [k][n], padded
    int tid = threadIdx.x;
    int bm = blockIdx.y, bn = blockIdx.x;
    int tm = tid >> 4, tn = tid & 15;

    int arow  = bm*128 + (tid >> 1);
    int acol0 = (tid & 1) * 4;
    int brow0 = tid >> 5;
    int bcol  = bn*128 + (tid & 31) * 4;
    const float* Ap = A + (size_t)arow * K + acol0;
    const float* Bp = B + (size_t)brow0 * N + bcol;

    float acc[8][8];
#pragma unroll
    for (int i = 0; i < 8; i++)
#pragma unroll
        for (int j = 0; j < 8; j++) acc[i][j] = 0.f;

    for (int kt = 0; kt < K; kt += 8) {
        float4 av = *(const float4*)(Ap + kt);
        float4 bv = *(const float4*)(Bp + (size_t)kt * N);
        __syncthreads();
        As[acol0 + 0][tid >> 1] = av.x;
        As[acol0 + 1][tid >> 1] = av.y;
        As[acol0 + 2][tid >> 1] = av.z;
        As[acol0 + 3][tid >> 1] = av.w;
        *(float4*)&Bs[brow0][(tid & 31) * 4] = bv;
        __syncthreads();
#pragma unroll
        for (int k = 0; k < 8; k++) {
            float4 a0 = *(const float4*)&As[k][tm*4];
            float4 a1 = *(const float4*)&As[k][tm*4 + 64];
            float4 b0 = *(const float4*)&Bs[k][tn*4];
            float4 b1 = *(const float4*)&Bs[k][tn*4 + 64];
            float ar[8] = {a0.x,a0.y,a0.z,a0.w,a1.x,a1.y,a1.z,a1.w};
            float br[8] = {b0.x,b0.y,b0.z,b0.w,b1.x,b1.y,b1.z,b1.w};
#pragma unroll
            for (int i = 0; i < 8; i++)
#pragma unroll
                for (int j = 0; j < 8; j++) acc[i][j] += ar[i] * br[j];
        }
    }

    int row0 = bm*128 + tm*4;
    int col0 = bn*128 + tn*4;
#pragma unroll
    for (int ih = 0; ih < 2; ih++) {
#pragma unroll
        for (int ii = 0; ii < 4; ii++) {
            int r = row0 + ih*64 + ii;
            size_t rbase = (size_t)r * N;
#pragma unroll
            for (int jh = 0; jh < 2; jh++) {
                int c = col0 + jh*64;
                float vv[4];
#pragma unroll
                for (int jj = 0; jj < 4; jj++) {
                    float v = acc[ih*4 + ii][jh*4 + jj] + bias[c + jj];
                    if (epi == 2) {
                        v = 0.5f * v * (1.0f + erff(v * 0.70710678118654752440f));
                    } else if (epi == 1) {
                        v += res[rbase + c + jj];
                    }
                    vv[jj] = v;
                }
                float4 o4 = {vv[0], vv[1], vv[2], vv[3]};
                *(float4*)&C[rbase + c] = o4;
            }
        }
    }
}

// ---------------------------------------------------------------------------
// Flash-style attention per (b, h, 64-query tile). K is also the value matrix
// (reference quirk). Q,K in token-major layout [tok][h*64 + dk].
// 256 threads: thread(ty 0..15, tx 0..15) owns q-rows 4ty..+3.
// S-tile: 64q x 32k (2 cols/thread), O: 64q x 64d (4 cols/thread).
// Online softmax, row reduce via half-warp shuffles (lanes of same ty group).
// ---------------------------------------------------------------------------
__global__ void __launch_bounds__(256) attn_kernel(
    const float* __restrict__ Q, const float* __restrict__ K,
    const int* __restrict__ mask, float* __restrict__ O)
{
    __shared__ float Qs[64*68];     // [d][q]
    __shared__ float Ksdj[64*36];   // [d][j]
    __shared__ float Ksjd[32*68];   // [j][d]
    __shared__ float Ps[32*68];     // [j][q]
    __shared__ int   msk[32];

    int b = blockIdx.z, h = blockIdx.y;
    int q0 = blockIdx.x * 64;
    int tid = threadIdx.x;
    int ty = tid >> 4, tx = tid & 15;
    size_t base = (size_t)b * SS * DD + (size_t)h * DKK;

    for (int e = tid; e < 64*64; e += 256) {
        int q = e >> 6, d = e & 63;
        Qs[d*68 + q] = Q[base + (size_t)(q0 + q) * DD + d];
    }

    float m_[4], l_[4], o_[4][4];
#pragma unroll
    for (int i = 0; i < 4; i++) {
        m_[i] = -INFINITY; l_[i] = 0.f;
#pragma unroll
        for (int j = 0; j < 4; j++) o_[i][j] = 0.f;
    }

    int jc0 = tx * 2, jc1 = tx * 2 + 1;

    for (int k0 = 0; k0 < SS; k0 += 32) {
        __syncthreads();   // previous O-gemm reads done before overwrite
        for (int e = tid; e < 32*64; e += 256) {
            int j = e >> 6, d = e & 63;
            float v = K[base + (size_t)(k0 + j) * DD + d];
            Ksdj[d*36 + j] = v;
            Ksjd[j*68 + d] = v;
        }
        if (tid < 32) msk[tid] = mask[b*SS + k0 + tid];
        __syncthreads();

        // S = Q K^T for this tile: per-thread 4 rows x 2 cols
        float s0[4] = {0.f,0.f,0.f,0.f}, s1[4] = {0.f,0.f,0.f,0.f};
#pragma unroll 8
        for (int d = 0; d < 64; d++) {
            float4 a = *(const float4*)&Qs[d*68 + ty*4];
            float b0v = Ksdj[d*36 + jc0];
            float b1v = Ksdj[d*36 + jc1];
            s0[0] += a.x*b0v; s0[1] += a.y*b0v; s0[2] += a.z*b0v; s0[3] += a.w*b0v;
            s1[0] += a.x*b1v; s1[1] += a.y*b1v; s1[2] += a.z*b1v; s1[3] += a.w*b1v;
        }

        bool mok0 = (msk[jc0] != 0);
        bool mok1 = (msk[jc1] != 0);
        const float sc = 0.125f;   // 1/sqrt(64)
#pragma unroll
        for (int i = 0; i < 4; i++) {
            float v0 = mok0 ? s0[i]*sc : -1e9f;
            float v1 = mok1 ? s1[i]*sc : -1e9f;
            float mloc = fmaxf(v0, v1);
#pragma unroll
            for (int o = 1; o < 16; o <<= 1)
                mloc = fmaxf(mloc, __shfl_xor_sync(0xffffffffu, mloc, o));
            float mnew = fmaxf(m_[i], mloc);
            float p0 = __expf(v0 - mnew);
            float p1 = __expf(v1 - mnew);
            float rs = p0 + p1;
#pragma unroll
            for (int o = 1; o < 16; o <<= 1)
                rs += __shfl_xor_sync(0xffffffffu, rs, o);
            float corr = __expf(m_[i] - mnew);
            l_[i] = l_[i] * corr + rs;
            m_[i] = mnew;
#pragma unroll
            for (int j = 0; j < 4; j++) o_[i][j] *= corr;
            Ps[jc0*68 + ty*4 + i] = p0;
            Ps[jc1*68 + ty*4 + i] = p1;
        }
        __syncthreads();

        // O += P @ K  (values == K), per-thread 4 rows x 4 d-cols
#pragma unroll 4
        for (int j = 0; j < 32; j++) {
            float4 a  = *(const float4*)&Ps[j*68 + ty*4];
            float4 bv = *(const float4*)&Ksjd[j*68 + tx*4];
            o_[0][0] += a.x*bv.x; o_[0][1] += a.x*bv.y; o_[0][2] += a.x*bv.z; o_[0][3] += a.x*bv.w;
            o_[1][0] += a.y*bv.x; o_[1][1] += a.y*bv.y; o_[1][2] += a.y*bv.z; o_[1][3] += a.y*bv.w;
            o_[2][0] += a.z*bv.x; o_[2][1] += a.z*bv.y; o_[2][2] += a.z*bv.z; o_[2][3] += a.z*bv.w;
            o_[3][0] += a.w*bv.x; o_[3][1] += a.w*bv.y; o_[3][2] += a.w*bv.z; o_[3][3] += a.w*bv.w;
        }
    }

#pragma unroll
    for (int i = 0; i < 4; i++) {
        float inv = 1.0f / l_[i];
        float4 o4 = { o_[i][0]*inv, o_[i][1]*inv, o_[i][2]*inv, o_[i][3]*inv };
        *(float4*)&O[base + (size_t)(q0 + ty*4 + i) * DD + tx*4] = o4;
    }
}

// ---------------------------------------------------------------------------
// Host driver (graph-capturable: kernel launches only)
// ---------------------------------------------------------------------------
extern "C" void kernel_launch(void* const* d_in, const int* in_sizes, int n_in,
                              void* d_out, int out_size)
{
    const float* x    = (const float*)d_in[0];
    const int*   mask = (const int*)  d_in[1];
    const float* Wq   = (const float*)d_in[2];
    const float* bq   = (const float*)d_in[3];
    const float* Wk   = (const float*)d_in[4];
    const float* bk   = (const float*)d_in[5];
    // d_in[6], d_in[7]: Wv, bv — dead code in the reference (values == keys)
    const float* Wo   = (const float*)d_in[8];
    const float* bo   = (const float*)d_in[9];
    const float* ln1g = (const float*)d_in[10];
    const float* ln1b = (const float*)d_in[11];
    const float* W1   = (const float*)d_in[12];
    const float* b1   = (const float*)d_in[13];
    const float* W2   = (const float*)d_in[14];
    const float* b2   = (const float*)d_in[15];
    const float* ln2g = (const float*)d_in[16];
    const float* ln2b = (const float*)d_in[17];
    float* out = (float*)d_out;

    float *hid, *qb, *kb, *attn, *x2, *h2, *ffn;
    cudaGetSymbolAddress((void**)&hid,  g_hidden);
    cudaGetSymbolAddress((void**)&qb,   g_q);
    cudaGetSymbolAddress((void**)&kb,   g_k);
    cudaGetSymbolAddress((void**)&attn, g_attn);
    cudaGetSymbolAddress((void**)&x2,   g_x2);
    cudaGetSymbolAddress((void**)&h2,   g_h2);
    cudaGetSymbolAddress((void**)&ffn,  g_ffn);

    dim3 gD (DD  /128, NTOK/128);   // [8192,1024] outputs
    dim3 gFF(DFFC/128, NTOK/128);   // [8192,4096] outputs

    // 1) LN1
    ln_kernel<<<NTOK, 256>>>(x, ln1g, ln1b, hid);
    // 2) Q, K projections
    sgemm_kernel<<<gD, 256>>>(hid, Wq, bq, nullptr, qb, NTOK, DD, DD, 0);
    sgemm_kernel<<<gD, 256>>>(hid, Wk, bk, nullptr, kb, NTOK, DD, DD, 0);
    // 3) attention (values == K)
    attn_kernel<<<dim3(SS/64, HH, BB), 256>>>(qb, kb, mask, attn);
    // 4) output projection + residual
    sgemm_kernel<<<gD, 256>>>(attn, Wo, bo, x, x2, NTOK, DD, DD, 1);
    // 5) LN2
    ln_kernel<<<NTOK, 256>>>(x2, ln2g, ln2b, h2);
    // 6) FFN up + exact GELU
    sgemm_kernel<<<gFF, 256>>>(h2, W1, b1, nullptr, ffn, NTOK, DFFC, DD, 2);
    // 7) FFN down + residual -> final output
    sgemm_kernel<<<gD, 256>>>(ffn, W2, b2, x2, out, NTOK, DD, DFFC, 1);
}

// round 3
// speedup vs baseline: 1.7215x; 1.7215x over previous
#include <cuda_runtime.h>
#include <math.h>
#include <stdint.h>

#define BB   4
#define SS   2048
#define DD   1024
#define HH   16
#define DKK  64
#define DFFC 4096
#define NTOK (BB*SS)

// ---------------------------------------------------------------------------
// Scratch (allocation-free rule: __device__ globals)
// ---------------------------------------------------------------------------
__device__ float g_hidden[(size_t)NTOK*DD];
__device__ float g_q     [(size_t)NTOK*DD];
__device__ float g_k     [(size_t)NTOK*DD];
__device__ float g_attn  [(size_t)NTOK*DD];
__device__ float g_x2    [(size_t)NTOK*DD];
__device__ float g_h2    [(size_t)NTOK*DD];
__device__ float g_ffn   [(size_t)NTOK*DFFC];
// transposed weights [N,K] so both GEMM operands are K-major
__device__ float g_wqT[(size_t)DD*DD];
__device__ float g_wkT[(size_t)DD*DD];
__device__ float g_woT[(size_t)DD*DD];
__device__ float g_w1T[(size_t)DFFC*DD];
__device__ float g_w2T[(size_t)DD*DFFC];

// ---------------------------------------------------------------------------
// Helpers
// ---------------------------------------------------------------------------
__device__ __forceinline__ uint32_t smem_u32(const void* p) {
    uint32_t a;
    asm("{ .reg .u64 t; cvta.to.shared.u64 t, %1; cvt.u32.u64 %0, t; }"
        : "=r"(a) : "l"(p));
    return a;
}

// round-to-nearest tf32 (zeroes low 13 mantissa bits) — applied at producers
__device__ __forceinline__ float to_tf32(float x) {
    asm("cvt.rna.tf32.f32 %0, %0;" : "+f"(x));
    return x;
}

__device__ __forceinline__ void ldsm4(uint32_t& r0, uint32_t& r1,
                                      uint32_t& r2, uint32_t& r3, uint32_t addr) {
    asm volatile("ldmatrix.sync.aligned.m8n8.x4.shared.b16 {%0,%1,%2,%3}, [%4];"
                 : "=r"(r0), "=r"(r1), "=r"(r2), "=r"(r3) : "r"(addr));
}

__device__ __forceinline__ void mma_tf32(float* c, const uint32_t* a, const uint32_t* b) {
    asm volatile(
        "mma.sync.aligned.m16n8k8.row.col.f32.tf32.tf32.f32 "
        "{%0,%1,%2,%3}, {%4,%5,%6,%7}, {%8,%9}, {%0,%1,%2,%3};"
        : "+f"(c[0]), "+f"(c[1]), "+f"(c[2]), "+f"(c[3])
        : "r"(a[0]), "r"(a[1]), "r"(a[2]), "r"(a[3]), "r"(b[0]), "r"(b[1]));
}

// ---------------------------------------------------------------------------
// Weight transpose  WT[n][k] = tf32(W[k][n])
// ---------------------------------------------------------------------------
__global__ void __launch_bounds__(256) transpose_kernel(
    const float* __restrict__ W, float* __restrict__ WT, int K, int N)
{
    __shared__ float tile[32][33];
    int kb = blockIdx.y * 32, nb = blockIdx.x * 32;
    int tx = threadIdx.x & 31, ty = threadIdx.x >> 5;
#pragma unroll
    for (int i = 0; i < 32; i += 8)
        tile[ty + i][tx] = W[(size_t)(kb + ty + i) * N + nb + tx];
    __syncthreads();
#pragma unroll
    for (int i = 0; i < 32; i += 8)
        WT[(size_t)(nb + ty + i) * K + kb + tx] = to_tf32(tile[tx][ty + i]);
}

// ---------------------------------------------------------------------------
// Tensor-core tf32 GEMM: C[M,N] = A[M,K] @ BT[N,K]^T (+bias, +res / GELU)
// 128x128x32 tile, 256 threads (8 warps 4m x 2n, warp tile 32x64).
// mma.sync.m16n8k8 tf32; fragments via ldmatrix b16-pair trick; SW128 swizzle.
// epi: 0 = +bias ; 1 = +bias+residual ; 2 = gelu_exact(+bias), tf32-rounded
// ---------------------------------------------------------------------------
__global__ void __launch_bounds__(256) tc_gemm_kernel(
    const float* __restrict__ A, const float* __restrict__ BT,
    const float* __restrict__ bias, const float* __restrict__ res,
    float* __restrict__ C, int M, int N, int K, int epi)
{
    __shared__ float sA[128*32];
    __shared__ float sB[128*32];

    const int tid  = threadIdx.x;
    const int lane = tid & 31;
    const int wid  = tid >> 5;
    const int wm   = wid & 3;      // warp m index (0..3) -> 32 rows
    const int wn   = wid >> 2;     // warp n index (0..1) -> 64 cols
    const int m0   = blockIdx.y * 128;
    const int n0   = blockIdx.x * 128;

    float acc[2][8][4];
#pragma unroll
    for (int mt = 0; mt < 2; mt++)
#pragma unroll
        for (int nt = 0; nt < 8; nt++)
#pragma unroll
            for (int i = 0; i < 4; i++) acc[mt][nt][i] = 0.f;

    // fill-stage mapping: float4 slot v = tid + i*256; row = v>>3, kgroup = v&7
    int r_[4], c_[4];
    uint32_t stoff[4];
#pragma unroll
    for (int i = 0; i < 4; i++) {
        int v = tid + i * 256;
        r_[i] = v >> 3;
        c_[i] = v & 7;
        stoff[i] = (uint32_t)(r_[i] * 128 + ((c_[i] ^ (r_[i] & 7)) << 4));
    }

    const float* Ag = A  + (size_t)m0 * K;
    const float* Bg = BT + (size_t)n0 * K;

    float4 ra[4], rb[4];
#pragma unroll
    for (int i = 0; i < 4; i++) {
        ra[i] = *(const float4*)(Ag + (size_t)r_[i] * K + c_[i] * 4);
        rb[i] = *(const float4*)(Bg + (size_t)r_[i] * K + c_[i] * 4);
    }

    const uint32_t sAb = smem_u32(sA);
    const uint32_t sBb = smem_u32(sB);

    // fragment-load row constants
    const int q  = lane >> 3;      // quadrant
    const int r8 = lane & 7;
    int mA[2], nB[4];
#pragma unroll
    for (int mt = 0; mt < 2; mt++) mA[mt] = wm * 32 + mt * 16 + (q & 1) * 8 + r8;
#pragma unroll
    for (int nt2 = 0; nt2 < 4; nt2++) nB[nt2] = wn * 64 + nt2 * 16 + (q >> 1) * 8 + r8;

    const int nkt = K >> 5;
    for (int kt = 0; kt < nkt; kt++) {
        __syncthreads();
#pragma unroll
        for (int i = 0; i < 4; i++) {
            *(float4*)((char*)sA + stoff[i]) = ra[i];
            *(float4*)((char*)sB + stoff[i]) = rb[i];
        }
        __syncthreads();
        if (kt + 1 < nkt) {
            const float* Ag2 = Ag + (kt + 1) * 32;
            const float* Bg2 = Bg + (kt + 1) * 32;
#pragma unroll
            for (int i = 0; i < 4; i++) {
                ra[i] = *(const float4*)(Ag2 + (size_t)r_[i] * K + c_[i] * 4);
                rb[i] = *(const float4*)(Bg2 + (size_t)r_[i] * K + c_[i] * 4);
            }
        }
#pragma unroll
        for (int ks = 0; ks < 4; ks++) {
            uint32_t af[2][4];
#pragma unroll
            for (int mt = 0; mt < 2; mt++) {
                int k4 = ks * 2 + (q >> 1);
                uint32_t ad = sAb + (uint32_t)(mA[mt] * 128 + ((k4 ^ (mA[mt] & 7)) << 4));
                ldsm4(af[mt][0], af[mt][1], af[mt][2], af[mt][3], ad);
            }
            uint32_t bf[8][2];
#pragma unroll
            for (int nt2 = 0; nt2 < 4; nt2++) {
                int k4 = ks * 2 + (q & 1);
                uint32_t bd = sBb + (uint32_t)(nB[nt2] * 128 + ((k4 ^ (nB[nt2] & 7)) << 4));
                ldsm4(bf[nt2*2][0], bf[nt2*2][1], bf[nt2*2+1][0], bf[nt2*2+1][1], bd);
            }
#pragma unroll
            for (int mt = 0; mt < 2; mt++)
#pragma unroll
                for (int nt = 0; nt < 8; nt++)
                    mma_tf32(acc[mt][nt], af[mt], bf[nt]);
        }
    }

    // epilogue: thread (g = lane>>2, tig = lane&3)
    const int g   = lane >> 2;
    const int tig = lane & 3;
#pragma unroll
    for (int mt = 0; mt < 2; mt++) {
#pragma unroll
        for (int h = 0; h < 2; h++) {
            int row = m0 + wm * 32 + mt * 16 + h * 8 + g;
            size_t rbase = (size_t)row * N;
#pragma unroll
            for (int nt = 0; nt < 8; nt++) {
                int col = n0 + wn * 64 + nt * 8 + tig * 2;
                float v0 = acc[mt][nt][h*2 + 0] + bias[col];
                float v1 = acc[mt][nt][h*2 + 1] + bias[col + 1];
                if (epi == 2) {
                    v0 = 0.5f * v0 * (1.0f + erff(v0 * 0.70710678118654752440f));
                    v1 = 0.5f * v1 * (1.0f + erff(v1 * 0.70710678118654752440f));
                    v0 = to_tf32(v0);   // feeds next GEMM as MMA operand
                    v1 = to_tf32(v1);
                } else if (epi == 1) {
                    v0 += res[rbase + col];
                    v1 += res[rbase + col + 1];
                }
                float2 o2 = { v0, v1 };
                *(float2*)(C + rbase + col) = o2;
            }
        }
    }
}

// ---------------------------------------------------------------------------
// LayerNorm (output rounded to tf32 — it is only consumed as an MMA operand)
// ---------------------------------------------------------------------------
__global__ void __launch_bounds__(256) ln_kernel(
    const float* __restrict__ x, const float* __restrict__ g,
    const float* __restrict__ b, float* __restrict__ out)
{
    __shared__ float red[20];
    int t = blockIdx.x;
    int tid = threadIdx.x;
    float4 v = ((const float4*)(x + (size_t)t*DD))[tid];
    float s  = v.x + v.y + v.z + v.w;
    float s2 = v.x*v.x + v.y*v.y + v.z*v.z + v.w*v.w;
#pragma unroll
    for (int o = 16; o; o >>= 1) {
        s  += __shfl_xor_sync(0xffffffffu, s,  o);
        s2 += __shfl_xor_sync(0xffffffffu, s2, o);
    }
    int w = tid >> 5, l = tid & 31;
    if (l == 0) { red[w] = s; red[8 + w] = s2; }
    __syncthreads();
    if (tid == 0) {
        float a = 0.f, c = 0.f;
#pragma unroll
        for (int i = 0; i < 8; i++) { a += red[i]; c += red[8 + i]; }
        red[16] = a; red[17] = c;
    }
    __syncthreads();
    float mean = red[16] * (1.0f / DD);
    float var  = red[17] * (1.0f / DD) - mean * mean;
    float inv  = rsqrtf(var + 1e-5f);
    float4 gv = ((const float4*)g)[tid];
    float4 bv = ((const float4*)b)[tid];
    float4 o4;
    o4.x = to_tf32((v.x - mean) * inv * gv.x + bv.x);
    o4.y = to_tf32((v.y - mean) * inv * gv.y + bv.y);
    o4.z = to_tf32((v.z - mean) * inv * gv.z + bv.z);
    o4.w = to_tf32((v.w - mean) * inv * gv.w + bv.w);
    ((float4*)(out + (size_t)t*DD))[tid] = o4;
}

// ---------------------------------------------------------------------------
// Flash-style attention (values == K reference quirk); output tf32-rounded
// ---------------------------------------------------------------------------
__global__ void __launch_bounds__(256) attn_kernel(
    const float* __restrict__ Q, const float* __restrict__ K,
    const int* __restrict__ mask, float* __restrict__ O)
{
    __shared__ float Qs[64*68];
    __shared__ float Ksdj[64*36];
    __shared__ float Ksjd[32*68];
    __shared__ float Ps[32*68];
    __shared__ int   msk[32];

    int b = blockIdx.z, h = blockIdx.y;
    int q0 = blockIdx.x * 64;
    int tid = threadIdx.x;
    int ty = tid >> 4, tx = tid & 15;
    size_t base = (size_t)b * SS * DD + (size_t)h * DKK;

    for (int e = tid; e < 64*64; e += 256) {
        int q = e >> 6, d = e & 63;
        Qs[d*68 + q] = Q[base + (size_t)(q0 + q) * DD + d];
    }

    float m_[4], l_[4], o_[4][4];
#pragma unroll
    for (int i = 0; i < 4; i++) {
        m_[i] = -INFINITY; l_[i] = 0.f;
#pragma unroll
        for (int j = 0; j < 4; j++) o_[i][j] = 0.f;
    }

    int jc0 = tx * 2, jc1 = tx * 2 + 1;

    for (int k0 = 0; k0 < SS; k0 += 32) {
        __syncthreads();
        for (int e = tid; e < 32*64; e += 256) {
            int j = e >> 6, d = e & 63;
            float v = K[base + (size_t)(k0 + j) * DD + d];
            Ksdj[d*36 + j] = v;
            Ksjd[j*68 + d] = v;
        }
        if (tid < 32) msk[tid] = mask[b*SS + k0 + tid];
        __syncthreads();

        float s0[4] = {0.f,0.f,0.f,0.f}, s1[4] = {0.f,0.f,0.f,0.f};
#pragma unroll 8
        for (int d = 0; d < 64; d++) {
            float4 a = *(const float4*)&Qs[d*68 + ty*4];
            float b0v = Ksdj[d*36 + jc0];
            float b1v = Ksdj[d*36 + jc1];
            s0[0] += a.x*b0v; s0[1] += a.y*b0v; s0[2] += a.z*b0v; s0[3] += a.w*b0v;
            s1[0] += a.x*b1v; s1[1] += a.y*b1v; s1[2] += a.z*b1v; s1[3] += a.w*b1v;
        }

        bool mok0 = (msk[jc0] != 0);
        bool mok1 = (msk[jc1] != 0);
        const float sc = 0.125f;
#pragma unroll
        for (int i = 0; i < 4; i++) {
            float v0 = mok0 ? s0[i]*sc : -1e9f;
            float v1 = mok1 ? s1[i]*sc : -1e9f;
            float mloc = fmaxf(v0, v1);
#pragma unroll
            for (int o = 1; o < 16; o <<= 1)
                mloc = fmaxf(mloc, __shfl_xor_sync(0xffffffffu, mloc, o));
            float mnew = fmaxf(m_[i], mloc);
            float p0 = __expf(v0 - mnew);
            float p1 = __expf(v1 - mnew);
            float rs = p0 + p1;
#pragma unroll
            for (int o = 1; o < 16; o <<= 1)
                rs += __shfl_xor_sync(0xffffffffu, rs, o);
            float corr = __expf(m_[i] - mnew);
            l_[i] = l_[i] * corr + rs;
            m_[i] = mnew;
#pragma unroll
            for (int j = 0; j < 4; j++) o_[i][j] *= corr;
            Ps[jc0*68 + ty*4 + i] = p0;
            Ps[jc1*68 + ty*4 + i] = p1;
        }
        __syncthreads();

#pragma unroll 4
        for (int j = 0; j < 32; j++) {
            float4 a  = *(const float4*)&Ps[j*68 + ty*4];
            float4 bv = *(const float4*)&Ksjd[j*68 + tx*4];
            o_[0][0] += a.x*bv.x; o_[0][1] += a.x*bv.y; o_[0][2] += a.x*bv.z; o_[0][3] += a.x*bv.w;
            o_[1][0] += a.y*bv.x; o_[1][1] += a.y*bv.y; o_[1][2] += a.y*bv.z; o_[1][3] += a.y*bv.w;
            o_[2][0] += a.z*bv.x; o_[2][1] += a.z*bv.y; o_[2][2] += a.z*bv.z; o_[2][3] += a.z*bv.w;
            o_[3][0] += a.w*bv.x; o_[3][1] += a.w*bv.y; o_[3][2] += a.w*bv.z; o_[3][3] += a.w*bv.w;
        }
    }

#pragma unroll
    for (int i = 0; i < 4; i++) {
        float inv = 1.0f / l_[i];
        float4 o4 = { to_tf32(o_[i][0]*inv), to_tf32(o_[i][1]*inv),
                      to_tf32(o_[i][2]*inv), to_tf32(o_[i][3]*inv) };
        *(float4*)&O[base + (size_t)(q0 + ty*4 + i) * DD + tx*4] = o4;
    }
}

// ---------------------------------------------------------------------------
// Host driver (graph-capturable: kernel launches only)
// ---------------------------------------------------------------------------
extern "C" void kernel_launch(void* const* d_in, const int* in_sizes, int n_in,
                              void* d_out, int out_size)
{
    const float* x    = (const float*)d_in[0];
    const int*   mask = (const int*)  d_in[1];
    const float* Wq   = (const float*)d_in[2];
    const float* bq   = (const float*)d_in[3];
    const float* Wk   = (const float*)d_in[4];
    const float* bk   = (const float*)d_in[5];
    // d_in[6], d_in[7]: Wv, bv — dead code in the reference (values == keys)
    const float* Wo   = (const float*)d_in[8];
    const float* bo   = (const float*)d_in[9];
    const float* ln1g = (const float*)d_in[10];
    const float* ln1b = (const float*)d_in[11];
    const float* W1   = (const float*)d_in[12];
    const float* b1   = (const float*)d_in[13];
    const float* W2   = (const float*)d_in[14];
    const float* b2   = (const float*)d_in[15];
    const float* ln2g = (const float*)d_in[16];
    const float* ln2b = (const float*)d_in[17];
    float* out = (float*)d_out;

    float *hid, *qb, *kb, *attn, *x2, *h2, *ffn;
    float *wqT, *wkT, *woT, *w1T, *w2T;
    cudaGetSymbolAddress((void**)&hid,  g_hidden);
    cudaGetSymbolAddress((void**)&qb,   g_q);
    cudaGetSymbolAddress((void**)&kb,   g_k);
    cudaGetSymbolAddress((void**)&attn, g_attn);
    cudaGetSymbolAddress((void**)&x2,   g_x2);
    cudaGetSymbolAddress((void**)&h2,   g_h2);
    cudaGetSymbolAddress((void**)&ffn,  g_ffn);
    cudaGetSymbolAddress((void**)&wqT,  g_wqT);
    cudaGetSymbolAddress((void**)&wkT,  g_wkT);
    cudaGetSymbolAddress((void**)&woT,  g_woT);
    cudaGetSymbolAddress((void**)&w1T,  g_w1T);
    cudaGetSymbolAddress((void**)&w2T,  g_w2T);

    // 0) weight transposes (+ tf32 rounding)
    transpose_kernel<<<dim3(DD/32,   DD/32),   256>>>(Wq, wqT, DD,   DD);
    transpose_kernel<<<dim3(DD/32,   DD/32),   256>>>(Wk, wkT, DD,   DD);
    transpose_kernel<<<dim3(DD/32,   DD/32),   256>>>(Wo, woT, DD,   DD);
    transpose_kernel<<<dim3(DFFC/32, DD/32),   256>>>(W1, w1T, DD,   DFFC);
    transpose_kernel<<<dim3(DD/32,   DFFC/32), 256>>>(W2, w2T, DFFC, DD);

    dim3 gD (DD  /128, NTOK/128);
    dim3 gFF(DFFC/128, NTOK/128);

    // 1) LN1
    ln_kernel<<<NTOK, 256>>>(x, ln1g, ln1b, hid);
    // 2) Q, K projections (tensor-core tf32)
    tc_gemm_kernel<<<gD, 256>>>(hid, wqT, bq, nullptr, qb, NTOK, DD, DD, 0);
    tc_gemm_kernel<<<gD, 256>>>(hid, wkT, bk, nullptr, kb, NTOK, DD, DD, 0);
    // 3) attention (values == K)
    attn_kernel<<<dim3(SS/64, HH, BB), 256>>>(qb, kb, mask, attn);
    // 4) output projection + residual
    tc_gemm_kernel<<<gD, 256>>>(attn, woT, bo, x, x2, NTOK, DD, DD, 1);
    // 5) LN2
    ln_kernel<<<NTOK, 256>>>(x2, ln2g, ln2b, h2);
    // 6) FFN up + exact GELU
    tc_gemm_kernel<<<gFF, 256>>>(h2, w1T, b1, nullptr, ffn, NTOK, DFFC, DD, 2);
    // 7) FFN down + residual -> final output
    tc_gemm_kernel<<<gD, 256>>>(ffn, w2T, b2, x2, out, NTOK, DD, DFFC, 1);
}

// round 4
// speedup vs baseline: 2.9310x; 1.7026x over previous
#include <cuda_runtime.h>
#include <math.h>
#include <stdint.h>

#define BB   4
#define SS   2048
#define DD   1024
#define HH   16
#define DKK  64
#define DFFC 4096
#define NTOK (BB*SS)

// ---------------------------------------------------------------------------
// Scratch (allocation-free rule: __device__ globals)
// ---------------------------------------------------------------------------
__device__ float g_hidden[(size_t)NTOK*DD];
__device__ float g_q     [(size_t)NTOK*DD];
__device__ float g_k     [(size_t)NTOK*DD];
__device__ float g_attn  [(size_t)NTOK*DD];
__device__ float g_x2    [(size_t)NTOK*DD];
__device__ float g_h2    [(size_t)NTOK*DD];
__device__ float g_ffn   [(size_t)NTOK*DFFC];
// transposed weights [N,K] so both GEMM operands are K-major
__device__ float g_wqT[(size_t)DD*DD];
__device__ float g_wkT[(size_t)DD*DD];
__device__ float g_woT[(size_t)DD*DD];
__device__ float g_w1T[(size_t)DFFC*DD];
__device__ float g_w2T[(size_t)DD*DFFC];

// ---------------------------------------------------------------------------
// Helpers
// ---------------------------------------------------------------------------
__device__ __forceinline__ uint32_t smem_u32(const void* p) {
    uint32_t a;
    asm("{ .reg .u64 t; cvta.to.shared.u64 t, %1; cvt.u32.u64 %0, t; }"
        : "=r"(a) : "l"(p));
    return a;
}

// round-to-nearest tf32 — applied at producers
__device__ __forceinline__ float to_tf32(float x) {
    asm("cvt.rna.tf32.f32 %0, %0;" : "+f"(x));
    return x;
}

__device__ __forceinline__ void ldsm4(uint32_t& r0, uint32_t& r1,
                                      uint32_t& r2, uint32_t& r3, uint32_t addr) {
    asm volatile("ldmatrix.sync.aligned.m8n8.x4.shared.b16 {%0,%1,%2,%3}, [%4];"
                 : "=r"(r0), "=r"(r1), "=r"(r2), "=r"(r3) : "r"(addr));
}

__device__ __forceinline__ void mma_tf32(float* c, const uint32_t* a, const uint32_t* b) {
    asm volatile(
        "mma.sync.aligned.m16n8k8.row.col.f32.tf32.tf32.f32 "
        "{%0,%1,%2,%3}, {%4,%5,%6,%7}, {%8,%9}, {%0,%1,%2,%3};"
        : "+f"(c[0]), "+f"(c[1]), "+f"(c[2]), "+f"(c[3])
        : "r"(a[0]), "r"(a[1]), "r"(a[2]), "r"(a[3]), "r"(b[0]), "r"(b[1]));
}

// ---------------------------------------------------------------------------
// Weight transpose  WT[n][k] = tf32(W[k][n])
// ---------------------------------------------------------------------------
__global__ void __launch_bounds__(256) transpose_kernel(
    const float* __restrict__ W, float* __restrict__ WT, int K, int N)
{
    __shared__ float tile[32][33];
    int kb = blockIdx.y * 32, nb = blockIdx.x * 32;
    int tx = threadIdx.x & 31, ty = threadIdx.x >> 5;
#pragma unroll
    for (int i = 0; i < 32; i += 8)
        tile[ty + i][tx] = W[(size_t)(kb + ty + i) * N + nb + tx];
    __syncthreads();
#pragma unroll
    for (int i = 0; i < 32; i += 8)
        WT[(size_t)(nb + ty + i) * K + kb + tx] = to_tf32(tile[tx][ty + i]);
}

// ---------------------------------------------------------------------------
// Tensor-core tf32 GEMM (unchanged from R3, validated)
// ---------------------------------------------------------------------------
__global__ void __launch_bounds__(256) tc_gemm_kernel(
    const float* __restrict__ A, const float* __restrict__ BT,
    const float* __restrict__ bias, const float* __restrict__ res,
    float* __restrict__ C, int M, int N, int K, int epi)
{
    __shared__ float sA[128*32];
    __shared__ float sB[128*32];

    const int tid  = threadIdx.x;
    const int lane = tid & 31;
    const int wid  = tid >> 5;
    const int wm   = wid & 3;
    const int wn   = wid >> 2;
    const int m0   = blockIdx.y * 128;
    const int n0   = blockIdx.x * 128;

    float acc[2][8][4];
#pragma unroll
    for (int mt = 0; mt < 2; mt++)
#pragma unroll
        for (int nt = 0; nt < 8; nt++)
#pragma unroll
            for (int i = 0; i < 4; i++) acc[mt][nt][i] = 0.f;

    int r_[4], c_[4];
    uint32_t stoff[4];
#pragma unroll
    for (int i = 0; i < 4; i++) {
        int v = tid + i * 256;
        r_[i] = v >> 3;
        c_[i] = v & 7;
        stoff[i] = (uint32_t)(r_[i] * 128 + ((c_[i] ^ (r_[i] & 7)) << 4));
    }

    const float* Ag = A  + (size_t)m0 * K;
    const float* Bg = BT + (size_t)n0 * K;

    float4 ra[4], rb[4];
#pragma unroll
    for (int i = 0; i < 4; i++) {
        ra[i] = *(const float4*)(Ag + (size_t)r_[i] * K + c_[i] * 4);
        rb[i] = *(const float4*)(Bg + (size_t)r_[i] * K + c_[i] * 4);
    }

    const uint32_t sAb = smem_u32(sA);
    const uint32_t sBb = smem_u32(sB);

    const int q  = lane >> 3;
    const int r8 = lane & 7;
    int mA[2], nB[4];
#pragma unroll
    for (int mt = 0; mt < 2; mt++) mA[mt] = wm * 32 + mt * 16 + (q & 1) * 8 + r8;
#pragma unroll
    for (int nt2 = 0; nt2 < 4; nt2++) nB[nt2] = wn * 64 + nt2 * 16 + (q >> 1) * 8 + r8;

    const int nkt = K >> 5;
    for (int kt = 0; kt < nkt; kt++) {
        __syncthreads();
#pragma unroll
        for (int i = 0; i < 4; i++) {
            *(float4*)((char*)sA + stoff[i]) = ra[i];
            *(float4*)((char*)sB + stoff[i]) = rb[i];
        }
        __syncthreads();
        if (kt + 1 < nkt) {
            const float* Ag2 = Ag + (kt + 1) * 32;
            const float* Bg2 = Bg + (kt + 1) * 32;
#pragma unroll
            for (int i = 0; i < 4; i++) {
                ra[i] = *(const float4*)(Ag2 + (size_t)r_[i] * K + c_[i] * 4);
                rb[i] = *(const float4*)(Bg2 + (size_t)r_[i] * K + c_[i] * 4);
            }
        }
#pragma unroll
        for (int ks = 0; ks < 4; ks++) {
            uint32_t af[2][4];
#pragma unroll
            for (int mt = 0; mt < 2; mt++) {
                int k4 = ks * 2 + (q >> 1);
                uint32_t ad = sAb + (uint32_t)(mA[mt] * 128 + ((k4 ^ (mA[mt] & 7)) << 4));
                ldsm4(af[mt][0], af[mt][1], af[mt][2], af[mt][3], ad);
            }
            uint32_t bf[8][2];
#pragma unroll
            for (int nt2 = 0; nt2 < 4; nt2++) {
                int k4 = ks * 2 + (q & 1);
                uint32_t bd = sBb + (uint32_t)(nB[nt2] * 128 + ((k4 ^ (nB[nt2] & 7)) << 4));
                ldsm4(bf[nt2*2][0], bf[nt2*2][1], bf[nt2*2+1][0], bf[nt2*2+1][1], bd);
            }
#pragma unroll
            for (int mt = 0; mt < 2; mt++)
#pragma unroll
                for (int nt = 0; nt < 8; nt++)
                    mma_tf32(acc[mt][nt], af[mt], bf[nt]);
        }
    }

    const int g   = lane >> 2;
    const int tig = lane & 3;
#pragma unroll
    for (int mt = 0; mt < 2; mt++) {
#pragma unroll
        for (int h = 0; h < 2; h++) {
            int row = m0 + wm * 32 + mt * 16 + h * 8 + g;
            size_t rbase = (size_t)row * N;
#pragma unroll
            for (int nt = 0; nt < 8; nt++) {
                int col = n0 + wn * 64 + nt * 8 + tig * 2;
                float v0 = acc[mt][nt][h*2 + 0] + bias[col];
                float v1 = acc[mt][nt][h*2 + 1] + bias[col + 1];
                if (epi == 2) {
                    v0 = 0.5f * v0 * (1.0f + erff(v0 * 0.70710678118654752440f));
                    v1 = 0.5f * v1 * (1.0f + erff(v1 * 0.70710678118654752440f));
                    v0 = to_tf32(v0);
                    v1 = to_tf32(v1);
                } else if (epi == 1) {
                    v0 += res[rbase + col];
                    v1 += res[rbase + col + 1];
                }
                float2 o2 = { v0, v1 };
                *(float2*)(C + rbase + col) = o2;
            }
        }
    }
}

// ---------------------------------------------------------------------------
// LayerNorm (output tf32-rounded; consumed only as MMA operand)
// ---------------------------------------------------------------------------
__global__ void __launch_bounds__(256) ln_kernel(
    const float* __restrict__ x, const float* __restrict__ g,
    const float* __restrict__ b, float* __restrict__ out)
{
    __shared__ float red[20];
    int t = blockIdx.x;
    int tid = threadIdx.x;
    float4 v = ((const float4*)(x + (size_t)t*DD))[tid];
    float s  = v.x + v.y + v.z + v.w;
    float s2 = v.x*v.x + v.y*v.y + v.z*v.z + v.w*v.w;
#pragma unroll
    for (int o = 16; o; o >>= 1) {
        s  += __shfl_xor_sync(0xffffffffu, s,  o);
        s2 += __shfl_xor_sync(0xffffffffu, s2, o);
    }
    int w = tid >> 5, l = tid & 31;
    if (l == 0) { red[w] = s; red[8 + w] = s2; }
    __syncthreads();
    if (tid == 0) {
        float a = 0.f, c = 0.f;
#pragma unroll
        for (int i = 0; i < 8; i++) { a += red[i]; c += red[8 + i]; }
        red[16] = a; red[17] = c;
    }
    __syncthreads();
    float mean = red[16] * (1.0f / DD);
    float var  = red[17] * (1.0f / DD) - mean * mean;
    float inv  = rsqrtf(var + 1e-5f);
    float4 gv = ((const float4*)g)[tid];
    float4 bv = ((const float4*)b)[tid];
    float4 o4;
    o4.x = to_tf32((v.x - mean) * inv * gv.x + bv.x);
    o4.y = to_tf32((v.y - mean) * inv * gv.y + bv.y);
    o4.z = to_tf32((v.z - mean) * inv * gv.z + bv.z);
    o4.w = to_tf32((v.w - mean) * inv * gv.w + bv.w);
    ((float4*)(out + (size_t)t*DD))[tid] = o4;
}

// ---------------------------------------------------------------------------
// Tensor-core flash attention. values == K (reference quirk).
// 128q x 64k tiles, 256 threads (8 warps x 16 q-rows), m16n8k8 tf32.
// Smem (dynamic, 98560B): Qs[128][64] | Kjd[64][64] | Kdj[64][64] | Ps[128][64] | msk[64]
// All tiles use the XOR-16B-group swizzle: sw(k4,row) = (k4&8) | ((k4^row)&7)
// ---------------------------------------------------------------------------
__global__ void __launch_bounds__(256, 2) tc_attn_kernel(
    const float* __restrict__ Q, const float* __restrict__ K,
    const int* __restrict__ mask, float* __restrict__ O)
{
    extern __shared__ float dsm[];
    float* Qs  = dsm;            // [128][64] row=q
    float* Kjd = dsm + 8192;     // [64][64]  row=key j
    float* Kdj = dsm + 12288;    // [64][64]  row=d
    float* Ps  = dsm + 16384;    // [128][64] row=q, col=key
    int*   msk = (int*)(dsm + 24576);

    const int b = blockIdx.z, h = blockIdx.y;
    const int q0 = blockIdx.x * 128;
    const int tid = threadIdx.x;
    const int lane = tid & 31, wid = tid >> 5;
    const size_t base = (size_t)b * SS * DD + (size_t)h * DKK;

    const uint32_t sQ  = smem_u32(Qs);
    const uint32_t sKj = smem_u32(Kjd);
    const uint32_t sKd = smem_u32(Kdj);
    const uint32_t sP  = smem_u32(Ps);

    // load Q tile (128 rows x 64 floats), swizzled
#pragma unroll
    for (int i = 0; i < 8; i++) {
        int s = tid + i * 256;
        int r = s >> 4, k4 = s & 15;
        float4 v = *(const float4*)(Q + base + (size_t)(q0 + r) * DD + k4 * 4);
        int sw = (k4 & 8) | ((k4 ^ r) & 7);
        *(float4*)(Qs + r * 64 + sw * 4) = v;
    }

    const int q  = lane >> 3, r8 = lane & 7;
    const int g  = lane >> 2, tig = lane & 3;
    const int mA = wid * 16 + (q & 1) * 8 + r8;     // A-fragment row
    const uint32_t aQ = sQ + (uint32_t)mA * 256;
    const uint32_t aP = sP + (uint32_t)mA * 256;

    float m_[2] = { -INFINITY, -INFINITY };
    float l_[2] = { 0.f, 0.f };
    float accO[8][4];
#pragma unroll
    for (int nt = 0; nt < 8; nt++)
#pragma unroll
        for (int i = 0; i < 4; i++) accO[nt][i] = 0.f;

    for (int k0 = 0; k0 < SS; k0 += 64) {
        __syncthreads();   // prior-iter MMA reads of Kjd/Kdj complete
        // load K tile: row-major copy + transposed copy
#pragma unroll
        for (int i = 0; i < 4; i++) {
            int s = tid + i * 256;
            int j = s >> 4, k4 = s & 15;
            float4 v = *(const float4*)(K + base + (size_t)(k0 + j) * DD + k4 * 4);
            int sw = (k4 & 8) | ((k4 ^ j) & 7);
            *(float4*)(Kjd + j * 64 + sw * 4) = v;
            int k4j = j >> 2, jb = j & 3;
            float vv[4] = { v.x, v.y, v.z, v.w };
#pragma unroll
            for (int e = 0; e < 4; e++) {
                int d = k4 * 4 + e;
                int swd = (k4j & 8) | ((k4j ^ d) & 7);
                Kdj[d * 64 + swd * 4 + jb] = vv[e];
            }
        }
        if (tid < 64) msk[tid] = mask[b * SS + k0 + tid];
        __syncthreads();

        // ---- S = Q @ K^T (warp's 16 rows x 64 keys) ----
        float accS[8][4];
#pragma unroll
        for (int nt = 0; nt < 8; nt++)
#pragma unroll
            for (int i = 0; i < 4; i++) accS[nt][i] = 0.f;

#pragma unroll
        for (int ks = 0; ks < 8; ks++) {
            uint32_t af[4];
            {
                int k4 = ks * 2 + (q >> 1);
                int sw = (k4 & 8) | ((k4 ^ mA) & 7);
                ldsm4(af[0], af[1], af[2], af[3], aQ + sw * 16);
            }
            uint32_t bf[8][2];
#pragma unroll
            for (int nt2 = 0; nt2 < 4; nt2++) {
                int nB = nt2 * 16 + (q >> 1) * 8 + r8;
                int k4 = ks * 2 + (q & 1);
                int sw = (k4 & 8) | ((k4 ^ nB) & 7);
                ldsm4(bf[nt2*2][0], bf[nt2*2][1], bf[nt2*2+1][0], bf[nt2*2+1][1],
                      sKj + (uint32_t)nB * 256 + sw * 16);
            }
#pragma unroll
            for (int nt = 0; nt < 8; nt++) mma_tf32(accS[nt], af, bf[nt]);
        }

        // ---- masked scale + online softmax on fragments ----
        const float sc = 0.125f;   // 1/sqrt(64)
#pragma unroll
        for (int hh = 0; hh < 2; hh++) {
            float mloc = -INFINITY;
#pragma unroll
            for (int nt = 0; nt < 8; nt++) {
                int c0 = nt * 8 + 2 * tig;
                float v0 = msk[c0]     ? accS[nt][2*hh]   * sc : -1e9f;
                float v1 = msk[c0 + 1] ? accS[nt][2*hh+1] * sc : -1e9f;
                accS[nt][2*hh] = v0; accS[nt][2*hh+1] = v1;
                mloc = fmaxf(mloc, fmaxf(v0, v1));
            }
            mloc = fmaxf(mloc, __shfl_xor_sync(0xffffffffu, mloc, 1));
            mloc = fmaxf(mloc, __shfl_xor_sync(0xffffffffu, mloc, 2));
            float mnew = fmaxf(m_[hh], mloc);
            float rs = 0.f;
#pragma unroll
            for (int nt = 0; nt < 8; nt++) {
                float p0 = __expf(accS[nt][2*hh]   - mnew);
                float p1 = __expf(accS[nt][2*hh+1] - mnew);
                accS[nt][2*hh] = p0; accS[nt][2*hh+1] = p1;
                rs += p0 + p1;
            }
            rs += __shfl_xor_sync(0xffffffffu, rs, 1);
            rs += __shfl_xor_sync(0xffffffffu, rs, 2);
            float corr = __expf(m_[hh] - mnew);
            l_[hh] = l_[hh] * corr + rs;
            m_[hh] = mnew;
#pragma unroll
            for (int nt = 0; nt < 8; nt++) {
                accO[nt][2*hh]   *= corr;
                accO[nt][2*hh+1] *= corr;
            }
            // write P rows to smem (warp-private band)
            int r = wid * 16 + g + hh * 8;
#pragma unroll
            for (int nt = 0; nt < 8; nt++) {
                int c0 = nt * 8 + 2 * tig;
                int k4 = c0 >> 2;
                int sw = (k4 & 8) | ((k4 ^ r) & 7);
                float2 p2 = { accS[nt][2*hh], accS[nt][2*hh+1] };
                *(float2*)(Ps + r * 64 + sw * 4 + (c0 & 3)) = p2;
            }
        }
        __syncwarp();   // Ps band is warp-private: warp-level ordering suffices

        // ---- O += P @ K (values == K) ----
#pragma unroll
        for (int ks = 0; ks < 8; ks++) {
            uint32_t af[4];
            {
                int k4 = ks * 2 + (q >> 1);
                int sw = (k4 & 8) | ((k4 ^ mA) & 7);
                ldsm4(af[0], af[1], af[2], af[3], aP + sw * 16);
            }
            uint32_t bf[8][2];
#pragma unroll
            for (int nt2 = 0; nt2 < 4; nt2++) {
                int nB = nt2 * 16 + (q >> 1) * 8 + r8;   // d rows
                int k4 = ks * 2 + (q & 1);
                int sw = (k4 & 8) | ((k4 ^ nB) & 7);
                ldsm4(bf[nt2*2][0], bf[nt2*2][1], bf[nt2*2+1][0], bf[nt2*2+1][1],
                      sKd + (uint32_t)nB * 256 + sw * 16);
            }
#pragma unroll
            for (int nt = 0; nt < 8; nt++) mma_tf32(accO[nt], af, bf[nt]);
        }
    }

    // ---- normalize + store ----
#pragma unroll
    for (int hh = 0; hh < 2; hh++) {
        int r = wid * 16 + g + hh * 8;
        float inv = 1.0f / l_[hh];
        size_t rb = base + (size_t)(q0 + r) * DD;
#pragma unroll
        for (int nt = 0; nt < 8; nt++) {
            int c0 = nt * 8 + 2 * tig;
            float2 o2 = { to_tf32(accO[nt][2*hh]   * inv),
                          to_tf32(accO[nt][2*hh+1] * inv) };
            *(float2*)(O + rb + c0) = o2;
        }
    }
}

#define ATTN_SMEM (24576*4 + 256)

// ---------------------------------------------------------------------------
// Host driver (graph-capturable: kernel launches only)
// ---------------------------------------------------------------------------
extern "C" void kernel_launch(void* const* d_in, const int* in_sizes, int n_in,
                              void* d_out, int out_size)
{
    const float* x    = (const float*)d_in[0];
    const int*   mask = (const int*)  d_in[1];
    const float* Wq   = (const float*)d_in[2];
    const float* bq   = (const float*)d_in[3];
    const float* Wk   = (const float*)d_in[4];
    const float* bk   = (const float*)d_in[5];
    // d_in[6], d_in[7]: Wv, bv — dead code in the reference (values == keys)
    const float* Wo   = (const float*)d_in[8];
    const float* bo   = (const float*)d_in[9];
    const float* ln1g = (const float*)d_in[10];
    const float* ln1b = (const float*)d_in[11];
    const float* W1   = (const float*)d_in[12];
    const float* b1   = (const float*)d_in[13];
    const float* W2   = (const float*)d_in[14];
    const float* b2   = (const float*)d_in[15];
    const float* ln2g = (const float*)d_in[16];
    const float* ln2b = (const float*)d_in[17];
    float* out = (float*)d_out;

    float *hid, *qb, *kb, *attn, *x2, *h2, *ffn;
    float *wqT, *wkT, *woT, *w1T, *w2T;
    cudaGetSymbolAddress((void**)&hid,  g_hidden);
    cudaGetSymbolAddress((void**)&qb,   g_q);
    cudaGetSymbolAddress((void**)&kb,   g_k);
    cudaGetSymbolAddress((void**)&attn, g_attn);
    cudaGetSymbolAddress((void**)&x2,   g_x2);
    cudaGetSymbolAddress((void**)&h2,   g_h2);
    cudaGetSymbolAddress((void**)&ffn,  g_ffn);
    cudaGetSymbolAddress((void**)&wqT,  g_wqT);
    cudaGetSymbolAddress((void**)&wkT,  g_wkT);
    cudaGetSymbolAddress((void**)&woT,  g_woT);
    cudaGetSymbolAddress((void**)&w1T,  g_w1T);
    cudaGetSymbolAddress((void**)&w2T,  g_w2T);

    cudaFuncSetAttribute(tc_attn_kernel,
                         cudaFuncAttributeMaxDynamicSharedMemorySize, ATTN_SMEM);

    // 0) weight transposes (+ tf32 rounding)
    transpose_kernel<<<dim3(DD/32,   DD/32),   256>>>(Wq, wqT, DD,   DD);
    transpose_kernel<<<dim3(DD/32,   DD/32),   256>>>(Wk, wkT, DD,   DD);
    transpose_kernel<<<dim3(DD/32,   DD/32),   256>>>(Wo, woT, DD,   DD);
    transpose_kernel<<<dim3(DFFC/32, DD/32),   256>>>(W1, w1T, DD,   DFFC);
    transpose_kernel<<<dim3(DD/32,   DFFC/32), 256>>>(W2, w2T, DFFC, DD);

    dim3 gD (DD  /128, NTOK/128);
    dim3 gFF(DFFC/128, NTOK/128);

    // 1) LN1
    ln_kernel<<<NTOK, 256>>>(x, ln1g, ln1b, hid);
    // 2) Q, K projections (tensor-core tf32)
    tc_gemm_kernel<<<gD, 256>>>(hid, wqT, bq, nullptr, qb, NTOK, DD, DD, 0);
    tc_gemm_kernel<<<gD, 256>>>(hid, wkT, bk, nullptr, kb, NTOK, DD, DD, 0);
    // 3) attention (values == K), tensor-core flash
    tc_attn_kernel<<<dim3(SS/128, HH, BB), 256, ATTN_SMEM>>>(qb, kb, mask, attn);
    // 4) output projection + residual
    tc_gemm_kernel<<<gD, 256>>>(attn, woT, bo, x, x2, NTOK, DD, DD, 1);
    // 5) LN2
    ln_kernel<<<NTOK, 256>>>(x2, ln2g, ln2b, h2);
    // 6) FFN up + exact GELU
    tc_gemm_kernel<<<gFF, 256>>>(h2, w1T, b1, nullptr, ffn, NTOK, DFFC, DD, 2);
    // 7) FFN down + residual -> final output
    tc_gemm_kernel<<<gD, 256>>>(ffn, w2T, b2, x2, out, NTOK, DD, DFFC, 1);
}

// round 5
// speedup vs baseline: 3.8413x; 1.3106x over previous
#include <cuda_runtime.h>
#include <math.h>
#include <stdint.h>

#define BB   4
#define SS   2048
#define DD   1024
#define HH   16
#define DKK  64
#define DFFC 4096
#define NTOK (BB*SS)
#define QKLD (2*DD)

// ---------------------------------------------------------------------------
// Scratch (allocation-free rule: __device__ globals)
// ---------------------------------------------------------------------------
__device__ float g_hidden[(size_t)NTOK*DD];
__device__ float g_qk    [(size_t)NTOK*QKLD];
__device__ float g_attn  [(size_t)NTOK*DD];
__device__ float g_x2    [(size_t)NTOK*DD];
__device__ float g_h2    [(size_t)NTOK*DD];
__device__ float g_ffn   [(size_t)NTOK*DFFC];
// transposed weights [N,K]; wqkT holds Wq^T rows 0..1023, Wk^T rows 1024..2047
__device__ float g_wqkT[(size_t)QKLD*DD];
__device__ float g_woT [(size_t)DD*DD];
__device__ float g_w1T [(size_t)DFFC*DD];
__device__ float g_w2T [(size_t)DD*DFFC];
__device__ float g_bqk [QKLD];

// ---------------------------------------------------------------------------
// Helpers
// ---------------------------------------------------------------------------
__device__ __forceinline__ uint32_t smem_u32(const void* p) {
    uint32_t a;
    asm("{ .reg .u64 t; cvta.to.shared.u64 t, %1; cvt.u32.u64 %0, t; }"
        : "=r"(a) : "l"(p));
    return a;
}

__device__ __forceinline__ float to_tf32(float x) {
    asm("cvt.rna.tf32.f32 %0, %0;" : "+f"(x));
    return x;
}

__device__ __forceinline__ void ldsm4(uint32_t& r0, uint32_t& r1,
                                      uint32_t& r2, uint32_t& r3, uint32_t addr) {
    asm volatile("ldmatrix.sync.aligned.m8n8.x4.shared.b16 {%0,%1,%2,%3}, [%4];"
                 : "=r"(r0), "=r"(r1), "=r"(r2), "=r"(r3) : "r"(addr));
}

__device__ __forceinline__ void mma_tf32(float* c, const uint32_t* a, const uint32_t* b) {
    asm volatile(
        "mma.sync.aligned.m16n8k8.row.col.f32.tf32.tf32.f32 "
        "{%0,%1,%2,%3}, {%4,%5,%6,%7}, {%8,%9}, {%0,%1,%2,%3};"
        : "+f"(c[0]), "+f"(c[1]), "+f"(c[2]), "+f"(c[3])
        : "r"(a[0]), "r"(a[1]), "r"(a[2]), "r"(a[3]), "r"(b[0]), "r"(b[1]));
}

__device__ __forceinline__ void cpa16(uint32_t dst, const void* src) {
    asm volatile("cp.async.cg.shared.global [%0], [%1], 16;"
                 :: "r"(dst), "l"(src) : "memory");
}
#define CPA_COMMIT() asm volatile("cp.async.commit_group;" ::: "memory")
#define CPA_WAIT1()  asm volatile("cp.async.wait_group 1;"  ::: "memory")

// ---------------------------------------------------------------------------
// Weight transpose  WT[n][k] = tf32(W[k][n])
// ---------------------------------------------------------------------------
__global__ void __launch_bounds__(256) transpose_kernel(
    const float* __restrict__ W, float* __restrict__ WT, int K, int N)
{
    __shared__ float tile[32][33];
    int kb = blockIdx.y * 32, nb = blockIdx.x * 32;
    int tx = threadIdx.x & 31, ty = threadIdx.x >> 5;
#pragma unroll
    for (int i = 0; i < 32; i += 8)
        tile[ty + i][tx] = W[(size_t)(kb + ty + i) * N + nb + tx];
    __syncthreads();
#pragma unroll
    for (int i = 0; i < 32; i += 8)
        WT[(size_t)(nb + ty + i) * K + kb + tx] = to_tf32(tile[tx][ty + i]);
}

__global__ void concat_bias_kernel(const float* __restrict__ a,
                                   const float* __restrict__ b,
                                   float* __restrict__ dst)
{
    int i = blockIdx.x * 256 + threadIdx.x;
    if (i < DD) dst[i] = a[i];
    else if (i < QKLD) dst[i] = b[i - DD];
}

// ---------------------------------------------------------------------------
// Pipelined tensor-core tf32 GEMM: C[M,N] = A[M,K] @ BT[N,K]^T
// 128x128x32 tile, 3-stage cp.async pipeline, one __syncthreads per k-tile.
// Dynamic smem: A stages [3][128*32] then B stages [3][128*32] = 96 KB.
// epi: 0 = +bias ; 1 = +bias+residual ; 2 = gelu_exact(+bias), tf32-rounded
// ---------------------------------------------------------------------------
__global__ void __launch_bounds__(256, 2) tc_gemm_kernel(
    const float* __restrict__ A, const float* __restrict__ BT,
    const float* __restrict__ bias, const float* __restrict__ res,
    float* __restrict__ C, int M, int N, int K, int epi)
{
    extern __shared__ float dsm[];
    const uint32_t sAu = smem_u32(dsm);
    const uint32_t sBu = sAu + 3 * 16384;

    const int tid  = threadIdx.x;
    const int lane = tid & 31;
    const int wid  = tid >> 5;
    const int wm   = wid & 3;
    const int wn   = wid >> 2;
    const int m0   = blockIdx.y * 128;
    const int n0   = blockIdx.x * 128;

    float acc[2][8][4];
#pragma unroll
    for (int mt = 0; mt < 2; mt++)
#pragma unroll
        for (int nt = 0; nt < 8; nt++)
#pragma unroll
            for (int i = 0; i < 4; i++) acc[mt][nt][i] = 0.f;

    // copy mapping: float4 slot v = tid + i*256; row = v>>3, kgroup = v&7
    int r_[4], c_[4];
    uint32_t stoff[4];
#pragma unroll
    for (int i = 0; i < 4; i++) {
        int v = tid + i * 256;
        r_[i] = v >> 3;
        c_[i] = v & 7;
        stoff[i] = (uint32_t)(r_[i] * 128 + ((c_[i] ^ (r_[i] & 7)) << 4));
    }

    const float* Ag = A  + (size_t)m0 * K;
    const float* Bg = BT + (size_t)n0 * K;
    const int nkt = K >> 5;

    // prologue: tiles 0,1
#pragma unroll
    for (int p = 0; p < 2; p++) {
        uint32_t ab = sAu + p * 16384, bb = sBu + p * 16384;
        const float* Ag2 = Ag + p * 32;
        const float* Bg2 = Bg + p * 32;
#pragma unroll
        for (int i = 0; i < 4; i++) {
            cpa16(ab + stoff[i], Ag2 + (size_t)r_[i] * K + c_[i] * 4);
            cpa16(bb + stoff[i], Bg2 + (size_t)r_[i] * K + c_[i] * 4);
        }
        CPA_COMMIT();
    }

    const int q  = lane >> 3;
    const int r8 = lane & 7;
    int mA[2], nB[4];
#pragma unroll
    for (int mt = 0; mt < 2; mt++) mA[mt] = wm * 32 + mt * 16 + (q & 1) * 8 + r8;
#pragma unroll
    for (int nt2 = 0; nt2 < 4; nt2++) nB[nt2] = wn * 64 + nt2 * 16 + (q >> 1) * 8 + r8;

    int stg = 0;
    for (int kt = 0; kt < nkt; kt++) {
        CPA_WAIT1();
        __syncthreads();

        // issue copy for tile kt+2 into stage (kt+2)%3 (read at kt-1, now free)
        {
            int kt2 = kt + 2;
            if (kt2 < nkt) {
                int s2 = stg + 2; if (s2 >= 3) s2 -= 3;
                uint32_t ab = sAu + s2 * 16384, bb = sBu + s2 * 16384;
                const float* Ag2 = Ag + kt2 * 32;
                const float* Bg2 = Bg + kt2 * 32;
#pragma unroll
                for (int i = 0; i < 4; i++) {
                    cpa16(ab + stoff[i], Ag2 + (size_t)r_[i] * K + c_[i] * 4);
                    cpa16(bb + stoff[i], Bg2 + (size_t)r_[i] * K + c_[i] * 4);
                }
            }
            CPA_COMMIT();
        }

        const uint32_t sAb = sAu + stg * 16384;
        const uint32_t sBb = sBu + stg * 16384;
#pragma unroll
        for (int ks = 0; ks < 4; ks++) {
            uint32_t af[2][4];
#pragma unroll
            for (int mt = 0; mt < 2; mt++) {
                int k4 = ks * 2 + (q >> 1);
                uint32_t ad = sAb + (uint32_t)(mA[mt] * 128 + ((k4 ^ (mA[mt] & 7)) << 4));
                ldsm4(af[mt][0], af[mt][1], af[mt][2], af[mt][3], ad);
            }
            uint32_t bf[8][2];
#pragma unroll
            for (int nt2 = 0; nt2 < 4; nt2++) {
                int k4 = ks * 2 + (q & 1);
                uint32_t bd = sBb + (uint32_t)(nB[nt2] * 128 + ((k4 ^ (nB[nt2] & 7)) << 4));
                ldsm4(bf[nt2*2][0], bf[nt2*2][1], bf[nt2*2+1][0], bf[nt2*2+1][1], bd);
            }
#pragma unroll
            for (int mt = 0; mt < 2; mt++)
#pragma unroll
                for (int nt = 0; nt < 8; nt++)
                    mma_tf32(acc[mt][nt], af[mt], bf[nt]);
        }
        stg++; if (stg == 3) stg = 0;
    }

    const int g   = lane >> 2;
    const int tig = lane & 3;
#pragma unroll
    for (int mt = 0; mt < 2; mt++) {
#pragma unroll
        for (int h = 0; h < 2; h++) {
            int row = m0 + wm * 32 + mt * 16 + h * 8 + g;
            size_t rbase = (size_t)row * N;
#pragma unroll
            for (int nt = 0; nt < 8; nt++) {
                int col = n0 + wn * 64 + nt * 8 + tig * 2;
                float v0 = acc[mt][nt][h*2 + 0] + bias[col];
                float v1 = acc[mt][nt][h*2 + 1] + bias[col + 1];
                if (epi == 2) {
                    v0 = 0.5f * v0 * (1.0f + erff(v0 * 0.70710678118654752440f));
                    v1 = 0.5f * v1 * (1.0f + erff(v1 * 0.70710678118654752440f));
                    v0 = to_tf32(v0);
                    v1 = to_tf32(v1);
                } else if (epi == 1) {
                    v0 += res[rbase + col];
                    v1 += res[rbase + col + 1];
                }
                float2 o2 = { v0, v1 };
                *(float2*)(C + rbase + col) = o2;
            }
        }
    }
}
#define GEMM_SMEM (3*16384*2)

// ---------------------------------------------------------------------------
// LayerNorm (output tf32-rounded; consumed only as MMA operand)
// ---------------------------------------------------------------------------
__global__ void __launch_bounds__(256) ln_kernel(
    const float* __restrict__ x, const float* __restrict__ g,
    const float* __restrict__ b, float* __restrict__ out)
{
    __shared__ float red[20];
    int t = blockIdx.x;
    int tid = threadIdx.x;
    float4 v = ((const float4*)(x + (size_t)t*DD))[tid];
    float s  = v.x + v.y + v.z + v.w;
    float s2 = v.x*v.x + v.y*v.y + v.z*v.z + v.w*v.w;
#pragma unroll
    for (int o = 16; o; o >>= 1) {
        s  += __shfl_xor_sync(0xffffffffu, s,  o);
        s2 += __shfl_xor_sync(0xffffffffu, s2, o);
    }
    int w = tid >> 5, l = tid & 31;
    if (l == 0) { red[w] = s; red[8 + w] = s2; }
    __syncthreads();
    if (tid == 0) {
        float a = 0.f, c = 0.f;
#pragma unroll
        for (int i = 0; i < 8; i++) { a += red[i]; c += red[8 + i]; }
        red[16] = a; red[17] = c;
    }
    __syncthreads();
    float mean = red[16] * (1.0f / DD);
    float var  = red[17] * (1.0f / DD) - mean * mean;
    float inv  = rsqrtf(var + 1e-5f);
    float4 gv = ((const float4*)g)[tid];
    float4 bv = ((const float4*)b)[tid];
    float4 o4;
    o4.x = to_tf32((v.x - mean) * inv * gv.x + bv.x);
    o4.y = to_tf32((v.y - mean) * inv * gv.y + bv.y);
    o4.z = to_tf32((v.z - mean) * inv * gv.z + bv.z);
    o4.w = to_tf32((v.w - mean) * inv * gv.w + bv.w);
    ((float4*)(out + (size_t)t*DD))[tid] = o4;
}

// ---------------------------------------------------------------------------
// Tensor-core flash attention reading the fused QK buffer (row stride QKLD).
// Q at col h*64, K at col 1024 + h*64. values == K (reference quirk).
// 128q x 64k tiles, 256 threads, m16n8k8 tf32, XOR-16B swizzle.
// ---------------------------------------------------------------------------
__global__ void __launch_bounds__(256, 2) tc_attn_kernel(
    const float* __restrict__ QK, const int* __restrict__ mask,
    float* __restrict__ O)
{
    extern __shared__ float dsm[];
    float* Qs  = dsm;            // [128][64] row=q
    float* Kjd = dsm + 8192;     // [64][64]  row=key j
    float* Kdj = dsm + 12288;    // [64][64]  row=d
    float* Ps  = dsm + 16384;    // [128][64] row=q, col=key
    int*   msk = (int*)(dsm + 24576);

    const int b = blockIdx.z, h = blockIdx.y;
    const int q0 = blockIdx.x * 128;
    const int tid = threadIdx.x;
    const int lane = tid & 31, wid = tid >> 5;
    const size_t base_q = (size_t)b * SS * QKLD + (size_t)h * DKK;
    const size_t base_k = base_q + DD;
    const size_t base_o = (size_t)b * SS * DD + (size_t)h * DKK;

    const uint32_t sQ  = smem_u32(Qs);
    const uint32_t sKj = smem_u32(Kjd);
    const uint32_t sKd = smem_u32(Kdj);
    const uint32_t sP  = smem_u32(Ps);

#pragma unroll
    for (int i = 0; i < 8; i++) {
        int s = tid + i * 256;
        int r = s >> 4, k4 = s & 15;
        float4 v = *(const float4*)(QK + base_q + (size_t)(q0 + r) * QKLD + k4 * 4);
        int sw = (k4 & 8) | ((k4 ^ r) & 7);
        *(float4*)(Qs + r * 64 + sw * 4) = v;
    }

    const int q  = lane >> 3, r8 = lane & 7;
    const int g  = lane >> 2, tig = lane & 3;
    const int mA = wid * 16 + (q & 1) * 8 + r8;
    const uint32_t aQ = sQ + (uint32_t)mA * 256;
    const uint32_t aP = sP + (uint32_t)mA * 256;

    float m_[2] = { -INFINITY, -INFINITY };
    float l_[2] = { 0.f, 0.f };
    float accO[8][4];
#pragma unroll
    for (int nt = 0; nt < 8; nt++)
#pragma unroll
        for (int i = 0; i < 4; i++) accO[nt][i] = 0.f;

    for (int k0 = 0; k0 < SS; k0 += 64) {
        __syncthreads();
#pragma unroll
        for (int i = 0; i < 4; i++) {
            int s = tid + i * 256;
            int j = s >> 4, k4 = s & 15;
            float4 v = *(const float4*)(QK + base_k + (size_t)(k0 + j) * QKLD + k4 * 4);
            int sw = (k4 & 8) | ((k4 ^ j) & 7);
            *(float4*)(Kjd + j * 64 + sw * 4) = v;
            int k4j = j >> 2, jb = j & 3;
            float vv[4] = { v.x, v.y, v.z, v.w };
#pragma unroll
            for (int e = 0; e < 4; e++) {
                int d = k4 * 4 + e;
                int swd = (k4j & 8) | ((k4j ^ d) & 7);
                Kdj[d * 64 + swd * 4 + jb] = vv[e];
            }
        }
        if (tid < 64) msk[tid] = mask[b * SS + k0 + tid];
        __syncthreads();

        // S = Q @ K^T
        float accS[8][4];
#pragma unroll
        for (int nt = 0; nt < 8; nt++)
#pragma unroll
            for (int i = 0; i < 4; i++) accS[nt][i] = 0.f;

#pragma unroll
        for (int ks = 0; ks < 8; ks++) {
            uint32_t af[4];
            {
                int k4 = ks * 2 + (q >> 1);
                int sw = (k4 & 8) | ((k4 ^ mA) & 7);
                ldsm4(af[0], af[1], af[2], af[3], aQ + sw * 16);
            }
            uint32_t bf[8][2];
#pragma unroll
            for (int nt2 = 0; nt2 < 4; nt2++) {
                int nB = nt2 * 16 + (q >> 1) * 8 + r8;
                int k4 = ks * 2 + (q & 1);
                int sw = (k4 & 8) | ((k4 ^ nB) & 7);
                ldsm4(bf[nt2*2][0], bf[nt2*2][1], bf[nt2*2+1][0], bf[nt2*2+1][1],
                      sKj + (uint32_t)nB * 256 + sw * 16);
            }
#pragma unroll
            for (int nt = 0; nt < 8; nt++) mma_tf32(accS[nt], af, bf[nt]);
        }

        // masked scale + online softmax
        const float sc = 0.125f;
#pragma unroll
        for (int hh = 0; hh < 2; hh++) {
            float mloc = -INFINITY;
#pragma unroll
            for (int nt = 0; nt < 8; nt++) {
                int c0 = nt * 8 + 2 * tig;
                float v0 = msk[c0]     ? accS[nt][2*hh]   * sc : -1e9f;
                float v1 = msk[c0 + 1] ? accS[nt][2*hh+1] * sc : -1e9f;
                accS[nt][2*hh] = v0; accS[nt][2*hh+1] = v1;
                mloc = fmaxf(mloc, fmaxf(v0, v1));
            }
            mloc = fmaxf(mloc, __shfl_xor_sync(0xffffffffu, mloc, 1));
            mloc = fmaxf(mloc, __shfl_xor_sync(0xffffffffu, mloc, 2));
            float mnew = fmaxf(m_[hh], mloc);
            float rs = 0.f;
#pragma unroll
            for (int nt = 0; nt < 8; nt++) {
                float p0 = __expf(accS[nt][2*hh]   - mnew);
                float p1 = __expf(accS[nt][2*hh+1] - mnew);
                accS[nt][2*hh] = p0; accS[nt][2*hh+1] = p1;
                rs += p0 + p1;
            }
            rs += __shfl_xor_sync(0xffffffffu, rs, 1);
            rs += __shfl_xor_sync(0xffffffffu, rs, 2);
            float corr = __expf(m_[hh] - mnew);
            l_[hh] = l_[hh] * corr + rs;
            m_[hh] = mnew;
#pragma unroll
            for (int nt = 0; nt < 8; nt++) {
                accO[nt][2*hh]   *= corr;
                accO[nt][2*hh+1] *= corr;
            }
            int r = wid * 16 + g + hh * 8;
#pragma unroll
            for (int nt = 0; nt < 8; nt++) {
                int c0 = nt * 8 + 2 * tig;
                int k4 = c0 >> 2;
                int sw = (k4 & 8) | ((k4 ^ r) & 7);
                float2 p2 = { accS[nt][2*hh], accS[nt][2*hh+1] };
                *(float2*)(Ps + r * 64 + sw * 4 + (c0 & 3)) = p2;
            }
        }
        __syncwarp();

        // O += P @ K (values == K)
#pragma unroll
        for (int ks = 0; ks < 8; ks++) {
            uint32_t af[4];
            {
                int k4 = ks * 2 + (q >> 1);
                int sw = (k4 & 8) | ((k4 ^ mA) & 7);
                ldsm4(af[0], af[1], af[2], af[3], aP + sw * 16);
            }
            uint32_t bf[8][2];
#pragma unroll
            for (int nt2 = 0; nt2 < 4; nt2++) {
                int nB = nt2 * 16 + (q >> 1) * 8 + r8;
                int k4 = ks * 2 + (q & 1);
                int sw = (k4 & 8) | ((k4 ^ nB) & 7);
                ldsm4(bf[nt2*2][0], bf[nt2*2][1], bf[nt2*2+1][0], bf[nt2*2+1][1],
                      sKd + (uint32_t)nB * 256 + sw * 16);
            }
#pragma unroll
            for (int nt = 0; nt < 8; nt++) mma_tf32(accO[nt], af, bf[nt]);
        }
    }

#pragma unroll
    for (int hh = 0; hh < 2; hh++) {
        int r = wid * 16 + g + hh * 8;
        float inv = 1.0f / l_[hh];
        size_t rb = base_o + (size_t)(q0 + r) * DD;
#pragma unroll
        for (int nt = 0; nt < 8; nt++) {
            int c0 = nt * 8 + 2 * tig;
            float2 o2 = { to_tf32(accO[nt][2*hh]   * inv),
                          to_tf32(accO[nt][2*hh+1] * inv) };
            *(float2*)(O + rb + c0) = o2;
        }
    }
}
#define ATTN_SMEM (24576*4 + 256)

// ---------------------------------------------------------------------------
// Host driver (graph-capturable: kernel launches only)
// ---------------------------------------------------------------------------
extern "C" void kernel_launch(void* const* d_in, const int* in_sizes, int n_in,
                              void* d_out, int out_size)
{
    const float* x    = (const float*)d_in[0];
    const int*   mask = (const int*)  d_in[1];
    const float* Wq   = (const float*)d_in[2];
    const float* bq   = (const float*)d_in[3];
    const float* Wk   = (const float*)d_in[4];
    const float* bk   = (const float*)d_in[5];
    // d_in[6], d_in[7]: Wv, bv — dead code in the reference (values == keys)
    const float* Wo   = (const float*)d_in[8];
    const float* bo   = (const float*)d_in[9];
    const float* ln1g = (const float*)d_in[10];
    const float* ln1b = (const float*)d_in[11];
    const float* W1   = (const float*)d_in[12];
    const float* b1   = (const float*)d_in[13];
    const float* W2   = (const float*)d_in[14];
    const float* b2   = (const float*)d_in[15];
    const float* ln2g = (const float*)d_in[16];
    const float* ln2b = (const float*)d_in[17];
    float* out = (float*)d_out;

    float *hid, *qk, *attn, *x2, *h2, *ffn;
    float *wqkT, *woT, *w1T, *w2T, *bqk;
    cudaGetSymbolAddress((void**)&hid,  g_hidden);
    cudaGetSymbolAddress((void**)&qk,   g_qk);
    cudaGetSymbolAddress((void**)&attn, g_attn);
    cudaGetSymbolAddress((void**)&x2,   g_x2);
    cudaGetSymbolAddress((void**)&h2,   g_h2);
    cudaGetSymbolAddress((void**)&ffn,  g_ffn);
    cudaGetSymbolAddress((void**)&wqkT, g_wqkT);
    cudaGetSymbolAddress((void**)&woT,  g_woT);
    cudaGetSymbolAddress((void**)&w1T,  g_w1T);
    cudaGetSymbolAddress((void**)&w2T,  g_w2T);
    cudaGetSymbolAddress((void**)&bqk,  g_bqk);

    cudaFuncSetAttribute(tc_gemm_kernel,
                         cudaFuncAttributeMaxDynamicSharedMemorySize, GEMM_SMEM);
    cudaFuncSetAttribute(tc_attn_kernel,
                         cudaFuncAttributeMaxDynamicSharedMemorySize, ATTN_SMEM);

    // 0) weight transposes (+ tf32 rounding) and bias concat
    transpose_kernel<<<dim3(DD/32,   DD/32),   256>>>(Wq, wqkT, DD, DD);
    transpose_kernel<<<dim3(DD/32,   DD/32),   256>>>(Wk, wqkT + (size_t)DD*DD, DD, DD);
    transpose_kernel<<<dim3(DD/32,   DD/32),   256>>>(Wo, woT, DD,   DD);
    transpose_kernel<<<dim3(DFFC/32, DD/32),   256>>>(W1, w1T, DD,   DFFC);
    transpose_kernel<<<dim3(DD/32,   DFFC/32), 256>>>(W2, w2T, DFFC, DD);
    concat_bias_kernel<<<QKLD/256, 256>>>(bq, bk, bqk);

    dim3 gQK(QKLD/128, NTOK/128);
    dim3 gD (DD  /128, NTOK/128);
    dim3 gFF(DFFC/128, NTOK/128);

    // 1) LN1
    ln_kernel<<<NTOK, 256>>>(x, ln1g, ln1b, hid);
    // 2) fused Q+K projection (N=2048)
    tc_gemm_kernel<<<gQK, 256, GEMM_SMEM>>>(hid, wqkT, bqk, nullptr, qk, NTOK, QKLD, DD, 0);
    // 3) attention (values == K), tensor-core flash
    tc_attn_kernel<<<dim3(SS/128, HH, BB), 256, ATTN_SMEM>>>(qk, mask, attn);
    // 4) output projection + residual
    tc_gemm_kernel<<<gD, 256, GEMM_SMEM>>>(attn, woT, bo, x, x2, NTOK, DD, DD, 1);
    // 5) LN2
    ln_kernel<<<NTOK, 256>>>(x2, ln2g, ln2b, h2);
    // 6) FFN up + exact GELU
    tc_gemm_kernel<<<gFF, 256, GEMM_SMEM>>>(h2, w1T, b1, nullptr, ffn, NTOK, DFFC, DD, 2);
    // 7) FFN down + residual -> final output
    tc_gemm_kernel<<<gD, 256, GEMM_SMEM>>>(ffn, w2T, b2, x2, out, NTOK, DD, DFFC, 1);
}

// round 6
// speedup vs baseline: 4.0749x; 1.0608x over previous
#include <cuda_runtime.h>
#include <math.h>
#include <stdint.h>

#define BB   4
#define SS   2048
#define DD   1024
#define HH   16
#define DKK  64
#define DFFC 4096
#define NTOK (BB*SS)
#define QKLD (2*DD)

// ---------------------------------------------------------------------------
// Scratch (allocation-free rule: __device__ globals)
// ---------------------------------------------------------------------------
__device__ float g_hidden[(size_t)NTOK*DD];
__device__ float g_qk    [(size_t)NTOK*QKLD];
__device__ float g_attn  [(size_t)NTOK*DD];
__device__ float g_x2    [(size_t)NTOK*DD];
__device__ float g_h2    [(size_t)NTOK*DD];
__device__ float g_ffn   [(size_t)NTOK*DFFC];
__device__ float g_wqkT[(size_t)QKLD*DD];
__device__ float g_woT [(size_t)DD*DD];
__device__ float g_w1T [(size_t)DFFC*DD];
__device__ float g_w2T [(size_t)DD*DFFC];
__device__ float g_bqk [QKLD];

// ---------------------------------------------------------------------------
// Helpers
// ---------------------------------------------------------------------------
__device__ __forceinline__ uint32_t smem_u32(const void* p) {
    uint32_t a;
    asm("{ .reg .u64 t; cvta.to.shared.u64 t, %1; cvt.u32.u64 %0, t; }"
        : "=r"(a) : "l"(p));
    return a;
}

__device__ __forceinline__ float to_tf32(float x) {
    asm("cvt.rna.tf32.f32 %0, %0;" : "+f"(x));
    return x;
}

__device__ __forceinline__ void ldsm4(uint32_t& r0, uint32_t& r1,
                                      uint32_t& r2, uint32_t& r3, uint32_t addr) {
    asm volatile("ldmatrix.sync.aligned.m8n8.x4.shared.b16 {%0,%1,%2,%3}, [%4];"
                 : "=r"(r0), "=r"(r1), "=r"(r2), "=r"(r3) : "r"(addr));
}

__device__ __forceinline__ void mma_tf32(float* c, const uint32_t* a, const uint32_t* b) {
    asm volatile(
        "mma.sync.aligned.m16n8k8.row.col.f32.tf32.tf32.f32 "
        "{%0,%1,%2,%3}, {%4,%5,%6,%7}, {%8,%9}, {%0,%1,%2,%3};"
        : "+f"(c[0]), "+f"(c[1]), "+f"(c[2]), "+f"(c[3])
        : "r"(a[0]), "r"(a[1]), "r"(a[2]), "r"(a[3]), "r"(b[0]), "r"(b[1]));
}

__device__ __forceinline__ void cpa16(uint32_t dst, const void* src) {
    asm volatile("cp.async.cg.shared.global [%0], [%1], 16;"
                 :: "r"(dst), "l"(src) : "memory");
}
#define CPA_COMMIT() asm volatile("cp.async.commit_group;" ::: "memory")
#define CPA_WAIT1()  asm volatile("cp.async.wait_group 1;"  ::: "memory")
#define CPA_WAIT0()  asm volatile("cp.async.wait_group 0;"  ::: "memory")

// ---------------------------------------------------------------------------
// Weight transpose  WT[n][k] = tf32(W[k][n])
// ---------------------------------------------------------------------------
__global__ void __launch_bounds__(256) transpose_kernel(
    const float* __restrict__ W, float* __restrict__ WT, int K, int N)
{
    __shared__ float tile[32][33];
    int kb = blockIdx.y * 32, nb = blockIdx.x * 32;
    int tx = threadIdx.x & 31, ty = threadIdx.x >> 5;
#pragma unroll
    for (int i = 0; i < 32; i += 8)
        tile[ty + i][tx] = W[(size_t)(kb + ty + i) * N + nb + tx];
    __syncthreads();
#pragma unroll
    for (int i = 0; i < 32; i += 8)
        WT[(size_t)(nb + ty + i) * K + kb + tx] = to_tf32(tile[tx][ty + i]);
}

__global__ void concat_bias_kernel(const float* __restrict__ a,
                                   const float* __restrict__ b,
                                   float* __restrict__ dst)
{
    int i = blockIdx.x * 256 + threadIdx.x;
    if (i < DD) dst[i] = a[i];
    else if (i < QKLD) dst[i] = b[i - DD];
}

// ---------------------------------------------------------------------------
// Pipelined tensor-core tf32 GEMM (unchanged from R5, validated)
// ---------------------------------------------------------------------------
__global__ void __launch_bounds__(256, 2) tc_gemm_kernel(
    const float* __restrict__ A, const float* __restrict__ BT,
    const float* __restrict__ bias, const float* __restrict__ res,
    float* __restrict__ C, int M, int N, int K, int epi)
{
    extern __shared__ float dsm[];
    const uint32_t sAu = smem_u32(dsm);
    const uint32_t sBu = sAu + 3 * 16384;

    const int tid  = threadIdx.x;
    const int lane = tid & 31;
    const int wid  = tid >> 5;
    const int wm   = wid & 3;
    const int wn   = wid >> 2;
    const int m0   = blockIdx.y * 128;
    const int n0   = blockIdx.x * 128;

    float acc[2][8][4];
#pragma unroll
    for (int mt = 0; mt < 2; mt++)
#pragma unroll
        for (int nt = 0; nt < 8; nt++)
#pragma unroll
            for (int i = 0; i < 4; i++) acc[mt][nt][i] = 0.f;

    int r_[4], c_[4];
    uint32_t stoff[4];
#pragma unroll
    for (int i = 0; i < 4; i++) {
        int v = tid + i * 256;
        r_[i] = v >> 3;
        c_[i] = v & 7;
        stoff[i] = (uint32_t)(r_[i] * 128 + ((c_[i] ^ (r_[i] & 7)) << 4));
    }

    const float* Ag = A  + (size_t)m0 * K;
    const float* Bg = BT + (size_t)n0 * K;
    const int nkt = K >> 5;

#pragma unroll
    for (int p = 0; p < 2; p++) {
        uint32_t ab = sAu + p * 16384, bb = sBu + p * 16384;
        const float* Ag2 = Ag + p * 32;
        const float* Bg2 = Bg + p * 32;
#pragma unroll
        for (int i = 0; i < 4; i++) {
            cpa16(ab + stoff[i], Ag2 + (size_t)r_[i] * K + c_[i] * 4);
            cpa16(bb + stoff[i], Bg2 + (size_t)r_[i] * K + c_[i] * 4);
        }
        CPA_COMMIT();
    }

    const int q  = lane >> 3;
    const int r8 = lane & 7;
    int mA[2], nB[4];
#pragma unroll
    for (int mt = 0; mt < 2; mt++) mA[mt] = wm * 32 + mt * 16 + (q & 1) * 8 + r8;
#pragma unroll
    for (int nt2 = 0; nt2 < 4; nt2++) nB[nt2] = wn * 64 + nt2 * 16 + (q >> 1) * 8 + r8;

    int stg = 0;
    for (int kt = 0; kt < nkt; kt++) {
        CPA_WAIT1();
        __syncthreads();

        {
            int kt2 = kt + 2;
            if (kt2 < nkt) {
                int s2 = stg + 2; if (s2 >= 3) s2 -= 3;
                uint32_t ab = sAu + s2 * 16384, bb = sBu + s2 * 16384;
                const float* Ag2 = Ag + kt2 * 32;
                const float* Bg2 = Bg + kt2 * 32;
#pragma unroll
                for (int i = 0; i < 4; i++) {
                    cpa16(ab + stoff[i], Ag2 + (size_t)r_[i] * K + c_[i] * 4);
                    cpa16(bb + stoff[i], Bg2 + (size_t)r_[i] * K + c_[i] * 4);
                }
            }
            CPA_COMMIT();
        }

        const uint32_t sAb = sAu + stg * 16384;
        const uint32_t sBb = sBu + stg * 16384;
#pragma unroll
        for (int ks = 0; ks < 4; ks++) {
            uint32_t af[2][4];
#pragma unroll
            for (int mt = 0; mt < 2; mt++) {
                int k4 = ks * 2 + (q >> 1);
                uint32_t ad = sAb + (uint32_t)(mA[mt] * 128 + ((k4 ^ (mA[mt] & 7)) << 4));
                ldsm4(af[mt][0], af[mt][1], af[mt][2], af[mt][3], ad);
            }
            uint32_t bf[8][2];
#pragma unroll
            for (int nt2 = 0; nt2 < 4; nt2++) {
                int k4 = ks * 2 + (q & 1);
                uint32_t bd = sBb + (uint32_t)(nB[nt2] * 128 + ((k4 ^ (nB[nt2] & 7)) << 4));
                ldsm4(bf[nt2*2][0], bf[nt2*2][1], bf[nt2*2+1][0], bf[nt2*2+1][1], bd);
            }
#pragma unroll
            for (int mt = 0; mt < 2; mt++)
#pragma unroll
                for (int nt = 0; nt < 8; nt++)
                    mma_tf32(acc[mt][nt], af[mt], bf[nt]);
        }
        stg++; if (stg == 3) stg = 0;
    }

    const int g   = lane >> 2;
    const int tig = lane & 3;
#pragma unroll
    for (int mt = 0; mt < 2; mt++) {
#pragma unroll
        for (int h = 0; h < 2; h++) {
            int row = m0 + wm * 32 + mt * 16 + h * 8 + g;
            size_t rbase = (size_t)row * N;
#pragma unroll
            for (int nt = 0; nt < 8; nt++) {
                int col = n0 + wn * 64 + nt * 8 + tig * 2;
                float v0 = acc[mt][nt][h*2 + 0] + bias[col];
                float v1 = acc[mt][nt][h*2 + 1] + bias[col + 1];
                if (epi == 2) {
                    v0 = 0.5f * v0 * (1.0f + erff(v0 * 0.70710678118654752440f));
                    v1 = 0.5f * v1 * (1.0f + erff(v1 * 0.70710678118654752440f));
                    v0 = to_tf32(v0);
                    v1 = to_tf32(v1);
                } else if (epi == 1) {
                    v0 += res[rbase + col];
                    v1 += res[rbase + col + 1];
                }
                float2 o2 = { v0, v1 };
                *(float2*)(C + rbase + col) = o2;
            }
        }
    }
}
#define GEMM_SMEM (3*16384*2)

// ---------------------------------------------------------------------------
// LayerNorm (unchanged)
// ---------------------------------------------------------------------------
__global__ void __launch_bounds__(256) ln_kernel(
    const float* __restrict__ x, const float* __restrict__ g,
    const float* __restrict__ b, float* __restrict__ out)
{
    __shared__ float red[20];
    int t = blockIdx.x;
    int tid = threadIdx.x;
    float4 v = ((const float4*)(x + (size_t)t*DD))[tid];
    float s  = v.x + v.y + v.z + v.w;
    float s2 = v.x*v.x + v.y*v.y + v.z*v.z + v.w*v.w;
#pragma unroll
    for (int o = 16; o; o >>= 1) {
        s  += __shfl_xor_sync(0xffffffffu, s,  o);
        s2 += __shfl_xor_sync(0xffffffffu, s2, o);
    }
    int w = tid >> 5, l = tid & 31;
    if (l == 0) { red[w] = s; red[8 + w] = s2; }
    __syncthreads();
    if (tid == 0) {
        float a = 0.f, c = 0.f;
#pragma unroll
        for (int i = 0; i < 8; i++) { a += red[i]; c += red[8 + i]; }
        red[16] = a; red[17] = c;
    }
    __syncthreads();
    float mean = red[16] * (1.0f / DD);
    float var  = red[17] * (1.0f / DD) - mean * mean;
    float inv  = rsqrtf(var + 1e-5f);
    float4 gv = ((const float4*)g)[tid];
    float4 bv = ((const float4*)b)[tid];
    float4 o4;
    o4.x = to_tf32((v.x - mean) * inv * gv.x + bv.x);
    o4.y = to_tf32((v.y - mean) * inv * gv.y + bv.y);
    o4.z = to_tf32((v.z - mean) * inv * gv.z + bv.z);
    o4.w = to_tf32((v.w - mean) * inv * gv.w + bv.w);
    ((float4*)(out + (size_t)t*DD))[tid] = o4;
}

// ---------------------------------------------------------------------------
// Tensor-core flash attention v2. values == K (reference quirk).
// 128q x 64k tiles, 256 threads, m16n8k8 tf32.
// - K tiles double-buffered via cp.async (one __syncthreads per tile)
// - No transposed K copy: P@K B-fragments come from Kjd via scalar LDS
//   (PTX B layout: b0 k=tig, b1 k=tig+4, n=group)
// - No P smem round-trip: S-acc fragment -> A fragment via 8 shfl + 4 sel
// Smem: Qs[128*64] | Kj[2][64*64] | msk[2][64]   (~66KB)
// ---------------------------------------------------------------------------
__global__ void __launch_bounds__(256, 2) tc_attn_kernel(
    const float* __restrict__ QK, const int* __restrict__ mask,
    float* __restrict__ O)
{
    extern __shared__ float dsm[];
    float* Qs = dsm;                  // [128][64]
    float* Kj = dsm + 8192;           // [2][64*64]
    int*   msk = (int*)(dsm + 16384); // [2][64]

    const int b = blockIdx.z, h = blockIdx.y;
    const int q0 = blockIdx.x * 128;
    const int tid = threadIdx.x;
    const int lane = tid & 31, wid = tid >> 5;
    const size_t base_q = (size_t)b * SS * QKLD + (size_t)h * DKK;
    const size_t base_k = base_q + DD;
    const size_t base_o = (size_t)b * SS * DD + (size_t)h * DKK;

    const uint32_t sQ = smem_u32(Qs);
    const uint32_t sK = smem_u32(Kj);
    const uint32_t sM = smem_u32(msk);

    // Q tile load (once), swizzled
#pragma unroll
    for (int i = 0; i < 8; i++) {
        int s = tid + i * 256;
        int r = s >> 4, k4 = s & 15;
        float4 v = *(const float4*)(QK + base_q + (size_t)(q0 + r) * QKLD + k4 * 4);
        int sw = (k4 & 8) | ((k4 ^ r) & 7);
        *(float4*)(Qs + r * 64 + sw * 4) = v;
    }

    // prologue: async K tile 0 + mask 0
#pragma unroll
    for (int i = 0; i < 4; i++) {
        int s = tid + i * 256;
        int j = s >> 4, k4 = s & 15;
        int sw = (k4 & 8) | ((k4 ^ j) & 7);
        cpa16(sK + (uint32_t)(j * 256 + sw * 16),
              QK + base_k + (size_t)j * QKLD + k4 * 4);
    }
    if (tid < 16) cpa16(sM + tid * 16, mask + b * SS + tid * 4);
    CPA_COMMIT();

    const int q  = lane >> 3, r8 = lane & 7;
    const int g  = lane >> 2, tig = lane & 3;
    const int mA = wid * 16 + (q & 1) * 8 + r8;
    const uint32_t aQ = sQ + (uint32_t)mA * 256;
    // shuffle sources for acc->A fragment conversion
    const int s1 = (lane & ~3) | (tig >> 1);
    const int s2 = s1 + 2;
    // scalar-LDS B addressing constants
    const int dlo = g & 3;
    const int k4b = g >> 2;

    float m_[2] = { -INFINITY, -INFINITY };
    float l_[2] = { 0.f, 0.f };
    float accO[8][4];
#pragma unroll
    for (int nt = 0; nt < 8; nt++)
#pragma unroll
        for (int i = 0; i < 4; i++) accO[nt][i] = 0.f;

    int buf = 0;
    for (int k0 = 0; k0 < SS; k0 += 64, buf ^= 1) {
        CPA_WAIT0();
        __syncthreads();   // K(buf) visible; all warps done reading buf^1

        // issue next K tile + mask into buf^1
        if (k0 + 64 < SS) {
            const float* src = QK + base_k + (size_t)(k0 + 64) * QKLD;
            uint32_t dstb = sK + (buf ^ 1) * 16384;
#pragma unroll
            for (int i = 0; i < 4; i++) {
                int s = tid + i * 256;
                int j = s >> 4, k4 = s & 15;
                int sw = (k4 & 8) | ((k4 ^ j) & 7);
                cpa16(dstb + (uint32_t)(j * 256 + sw * 16),
                      src + (size_t)j * QKLD + k4 * 4);
            }
            if (tid < 16)
                cpa16(sM + (buf ^ 1) * 256 + tid * 16,
                      mask + b * SS + k0 + 64 + tid * 4);
        }
        CPA_COMMIT();

        const uint32_t sKb = sK + buf * 16384;
        const float*  Kjb = Kj + buf * 4096;
        const int*    mkb = msk + buf * 64;

        // ---- S = Q @ K^T ----
        float accS[8][4];
#pragma unroll
        for (int nt = 0; nt < 8; nt++)
#pragma unroll
            for (int i = 0; i < 4; i++) accS[nt][i] = 0.f;

#pragma unroll
        for (int ks = 0; ks < 8; ks++) {
            uint32_t af[4];
            {
                int k4 = ks * 2 + (q >> 1);
                int sw = (k4 & 8) | ((k4 ^ mA) & 7);
                ldsm4(af[0], af[1], af[2], af[3], aQ + sw * 16);
            }
            uint32_t bf[8][2];
#pragma unroll
            for (int nt2 = 0; nt2 < 4; nt2++) {
                int nB = nt2 * 16 + (q >> 1) * 8 + r8;
                int k4 = ks * 2 + (q & 1);
                int sw = (k4 & 8) | ((k4 ^ nB) & 7);
                ldsm4(bf[nt2*2][0], bf[nt2*2][1], bf[nt2*2+1][0], bf[nt2*2+1][1],
                      sKb + (uint32_t)nB * 256 + sw * 16);
            }
#pragma unroll
            for (int nt = 0; nt < 8; nt++) mma_tf32(accS[nt], af, bf[nt]);
        }

        // ---- masked scale + online softmax on fragments ----
        const float sc = 0.125f;
#pragma unroll
        for (int hh = 0; hh < 2; hh++) {
            float mloc = -INFINITY;
#pragma unroll
            for (int nt = 0; nt < 8; nt++) {
                int c0 = nt * 8 + 2 * tig;
                float v0 = mkb[c0]     ? accS[nt][2*hh]   * sc : -1e9f;
                float v1 = mkb[c0 + 1] ? accS[nt][2*hh+1] * sc : -1e9f;
                accS[nt][2*hh] = v0; accS[nt][2*hh+1] = v1;
                mloc = fmaxf(mloc, fmaxf(v0, v1));
            }
            mloc = fmaxf(mloc, __shfl_xor_sync(0xffffffffu, mloc, 1));
            mloc = fmaxf(mloc, __shfl_xor_sync(0xffffffffu, mloc, 2));
            float mnew = fmaxf(m_[hh], mloc);
            float rs = 0.f;
#pragma unroll
            for (int nt = 0; nt < 8; nt++) {
                float p0 = __expf(accS[nt][2*hh]   - mnew);
                float p1 = __expf(accS[nt][2*hh+1] - mnew);
                accS[nt][2*hh] = p0; accS[nt][2*hh+1] = p1;
                rs += p0 + p1;
            }
            rs += __shfl_xor_sync(0xffffffffu, rs, 1);
            rs += __shfl_xor_sync(0xffffffffu, rs, 2);
            float corr = __expf(m_[hh] - mnew);
            l_[hh] = l_[hh] * corr + rs;
            m_[hh] = mnew;
#pragma unroll
            for (int nt = 0; nt < 8; nt++) {
                accO[nt][2*hh]   *= corr;
                accO[nt][2*hh+1] *= corr;
            }
        }

        // ---- O += P @ K (values == K) ----
        // k-block ks: A frag from accS[ks] via shuffles; B from Kjd scalar LDS
#pragma unroll
        for (int ks = 0; ks < 8; ks++) {
            float c0 = accS[ks][0], c1 = accS[ks][1];
            float c2 = accS[ks][2], c3 = accS[ks][3];
            float t0 = __shfl_sync(0xffffffffu, c0, s1);
            float t1 = __shfl_sync(0xffffffffu, c1, s1);
            float t2 = __shfl_sync(0xffffffffu, c2, s1);
            float t3 = __shfl_sync(0xffffffffu, c3, s1);
            float t4 = __shfl_sync(0xffffffffu, c0, s2);
            float t5 = __shfl_sync(0xffffffffu, c1, s2);
            float t6 = __shfl_sync(0xffffffffu, c2, s2);
            float t7 = __shfl_sync(0xffffffffu, c3, s2);
            bool odd = (tig & 1);
            uint32_t af[4];
            af[0] = __float_as_uint(odd ? t1 : t0);
            af[1] = __float_as_uint(odd ? t3 : t2);
            af[2] = __float_as_uint(odd ? t5 : t4);
            af[3] = __float_as_uint(odd ? t7 : t6);

            int j0 = ks * 8 + tig;          // b0 row
            int j1 = j0 + 4;                // b1 row
#pragma unroll
            for (int nt = 0; nt < 8; nt++) {
                int k4 = k4b + 2 * nt;
                int sw0 = (k4 & 8) | ((k4 ^ j0) & 7);
                int sw1 = (k4 & 8) | ((k4 ^ j1) & 7);
                uint32_t bf[2];
                bf[0] = __float_as_uint(Kjb[j0 * 64 + sw0 * 4 + dlo]);
                bf[1] = __float_as_uint(Kjb[j1 * 64 + sw1 * 4 + dlo]);
                mma_tf32(accO[nt], af, bf);
            }
        }
    }

    // ---- normalize + store ----
#pragma unroll
    for (int hh = 0; hh < 2; hh++) {
        int r = wid * 16 + g + hh * 8;
        float inv = 1.0f / l_[hh];
        size_t rb = base_o + (size_t)(q0 + r) * DD;
#pragma unroll
        for (int nt = 0; nt < 8; nt++) {
            int c0 = nt * 8 + 2 * tig;
            float2 o2 = { to_tf32(accO[nt][2*hh]   * inv),
                          to_tf32(accO[nt][2*hh+1] * inv) };
            *(float2*)(O + rb + c0) = o2;
        }
    }
}
#define ATTN_SMEM (16384*4 + 512)

// ---------------------------------------------------------------------------
// Host driver (graph-capturable: kernel launches only)
// ---------------------------------------------------------------------------
extern "C" void kernel_launch(void* const* d_in, const int* in_sizes, int n_in,
                              void* d_out, int out_size)
{
    const float* x    = (const float*)d_in[0];
    const int*   mask = (const int*)  d_in[1];
    const float* Wq   = (const float*)d_in[2];
    const float* bq   = (const float*)d_in[3];
    const float* Wk   = (const float*)d_in[4];
    const float* bk   = (const float*)d_in[5];
    // d_in[6], d_in[7]: Wv, bv — dead code in the reference (values == keys)
    const float* Wo   = (const float*)d_in[8];
    const float* bo   = (const float*)d_in[9];
    const float* ln1g = (const float*)d_in[10];
    const float* ln1b = (const float*)d_in[11];
    const float* W1   = (const float*)d_in[12];
    const float* b1   = (const float*)d_in[13];
    const float* W2   = (const float*)d_in[14];
    const float* b2   = (const float*)d_in[15];
    const float* ln2g = (const float*)d_in[16];
    const float* ln2b = (const float*)d_in[17];
    float* out = (float*)d_out;

    float *hid, *qk, *attn, *x2, *h2, *ffn;
    float *wqkT, *woT, *w1T, *w2T, *bqk;
    cudaGetSymbolAddress((void**)&hid,  g_hidden);
    cudaGetSymbolAddress((void**)&qk,   g_qk);
    cudaGetSymbolAddress((void**)&attn, g_attn);
    cudaGetSymbolAddress((void**)&x2,   g_x2);
    cudaGetSymbolAddress((void**)&h2,   g_h2);
    cudaGetSymbolAddress((void**)&ffn,  g_ffn);
    cudaGetSymbolAddress((void**)&wqkT, g_wqkT);
    cudaGetSymbolAddress((void**)&woT,  g_woT);
    cudaGetSymbolAddress((void**)&w1T,  g_w1T);
    cudaGetSymbolAddress((void**)&w2T,  g_w2T);
    cudaGetSymbolAddress((void**)&bqk,  g_bqk);

    cudaFuncSetAttribute(tc_gemm_kernel,
                         cudaFuncAttributeMaxDynamicSharedMemorySize, GEMM_SMEM);
    cudaFuncSetAttribute(tc_attn_kernel,
                         cudaFuncAttributeMaxDynamicSharedMemorySize, ATTN_SMEM);

    // 0) weight transposes (+ tf32 rounding) and bias concat
    transpose_kernel<<<dim3(DD/32,   DD/32),   256>>>(Wq, wqkT, DD, DD);
    transpose_kernel<<<dim3(DD/32,   DD/32),   256>>>(Wk, wqkT + (size_t)DD*DD, DD, DD);
    transpose_kernel<<<dim3(DD/32,   DD/32),   256>>>(Wo, woT, DD,   DD);
    transpose_kernel<<<dim3(DFFC/32, DD/32),   256>>>(W1, w1T, DD,   DFFC);
    transpose_kernel<<<dim3(DD/32,   DFFC/32), 256>>>(W2, w2T, DFFC, DD);
    concat_bias_kernel<<<QKLD/256, 256>>>(bq, bk, bqk);

    dim3 gQK(QKLD/128, NTOK/128);
    dim3 gD (DD  /128, NTOK/128);
    dim3 gFF(DFFC/128, NTOK/128);

    // 1) LN1
    ln_kernel<<<NTOK, 256>>>(x, ln1g, ln1b, hid);
    // 2) fused Q+K projection (N=2048)
    tc_gemm_kernel<<<gQK, 256, GEMM_SMEM>>>(hid, wqkT, bqk, nullptr, qk, NTOK, QKLD, DD, 0);
    // 3) attention (values == K), tensor-core flash v2
    tc_attn_kernel<<<dim3(SS/128, HH, BB), 256, ATTN_SMEM>>>(qk, mask, attn);
    // 4) output projection + residual
    tc_gemm_kernel<<<gD, 256, GEMM_SMEM>>>(attn, woT, bo, x, x2, NTOK, DD, DD, 1);
    // 5) LN2
    ln_kernel<<<NTOK, 256>>>(x2, ln2g, ln2b, h2);
    // 6) FFN up + exact GELU
    tc_gemm_kernel<<<gFF, 256, GEMM_SMEM>>>(h2, w1T, b1, nullptr, ffn, NTOK, DFFC, DD, 2);
    // 7) FFN down + residual -> final output
    tc_gemm_kernel<<<gD, 256, GEMM_SMEM>>>(ffn, w2T, b2, x2, out, NTOK, DD, DFFC, 1);
}